// round 10
// baseline (speedup 1.0000x reference)
#include <cuda_runtime.h>
#include <cuda_bf16.h>
#include <cuda_fp16.h>
#include <math.h>
#include <stdint.h>

#define GS    14
#define NQ    196            // GS*GS
#define CDIM  128
#define NH    4
#define HD    32
#define BATCH 1024
#define MTOT  (BATCH * NQ)   // 200704
#define KVN   384            // q(128) | k(128) | v(128)
#define TAB   729            // (2*GS-1)^2
#define NCP   208            // padded col count
#define SCALE 0.17677669529663688f   // 32^-0.5

// ---- scratch (static device allocations; no cudaMalloc allowed) ----
__device__ float g_qkv[(size_t)MTOT * KVN];   // ~308 MB
__device__ float g_att[(size_t)MTOT * CDIM];  // ~103 MB
__device__ float g_pos[TAB * NH];
__device__ float g_bias[NH * NQ * NCP];       // precomputed rpb, cols padded w/ -1e30
__device__ __nv_bfloat16 g_wqkv_h[KVN * CDIM];   // [n=384][k=128]
__device__ __nv_bfloat16 g_wqkv_l[KVN * CDIM];
__device__ __nv_bfloat16 g_wp_h[CDIM * CDIM];    // [n=128][k=128]
__device__ __nv_bfloat16 g_wp_l[CDIM * CDIM];

// ============================================================
// helpers
// ============================================================
__device__ __forceinline__ uint32_t smem_u32(const void* p) {
    uint32_t a;
    asm("{ .reg .u64 t; cvta.to.shared.u64 t, %1; cvt.u32.u64 %0, t; }"
        : "=r"(a) : "l"(p));
    return a;
}
__device__ __forceinline__ void ldsm_x4(uint32_t& r0, uint32_t& r1,
                                        uint32_t& r2, uint32_t& r3, uint32_t addr) {
    asm volatile("ldmatrix.sync.aligned.m8n8.x4.shared.b16 {%0,%1,%2,%3}, [%4];"
                 : "=r"(r0), "=r"(r1), "=r"(r2), "=r"(r3) : "r"(addr));
}
// bf16 mma (GEMMs)
__device__ __forceinline__ void mma16816(float* d, const uint32_t* a, const uint32_t* b) {
    asm volatile("mma.sync.aligned.m16n8k16.row.col.f32.bf16.bf16.f32 "
                 "{%0,%1,%2,%3}, {%4,%5,%6,%7}, {%8,%9}, {%0,%1,%2,%3};"
                 : "+f"(d[0]), "+f"(d[1]), "+f"(d[2]), "+f"(d[3])
                 : "r"(a[0]), "r"(a[1]), "r"(a[2]), "r"(a[3]),
                   "r"(b[0]), "r"(b[1]));
}
// fp16 mma (attention)
__device__ __forceinline__ void mma16816h(float* d, const uint32_t* a, const uint32_t* b) {
    asm volatile("mma.sync.aligned.m16n8k16.row.col.f32.f16.f16.f32 "
                 "{%0,%1,%2,%3}, {%4,%5,%6,%7}, {%8,%9}, {%0,%1,%2,%3};"
                 : "+f"(d[0]), "+f"(d[1]), "+f"(d[2]), "+f"(d[3])
                 : "r"(a[0]), "r"(a[1]), "r"(a[2]), "r"(a[3]),
                   "r"(b[0]), "r"(b[1]));
}
__device__ __forceinline__ void split2(float v0, float v1, uint32_t& hi, uint32_t& lo) {
    __nv_bfloat16 h0 = __float2bfloat16(v0), h1 = __float2bfloat16(v1);
    __nv_bfloat162 H = __halves2bfloat162(h0, h1);
    __nv_bfloat162 L = __halves2bfloat162(
        __float2bfloat16(v0 - __bfloat162float(h0)),
        __float2bfloat16(v1 - __bfloat162float(h1)));
    hi = *(uint32_t*)&H;
    lo = *(uint32_t*)&L;
}
__device__ __forceinline__ uint32_t pack2h(float v0, float v1) {
    __half2 H = __halves2half2(__float2half(v0), __float2half(v1));
    return *(uint32_t*)&H;
}
// swizzled byte offset inside a [rows]x128 bf16 tile (256B rows, 16B chunks)
__device__ __forceinline__ uint32_t swz(int row, int chunk) {
    return (uint32_t)(row * 256 + ((chunk ^ (row & 7)) << 4));
}
__device__ __forceinline__ void cpasync16(uint32_t saddr, const void* g) {
    asm volatile("cp.async.cg.shared.global [%0], [%1], 16;"
                 :: "r"(saddr), "l"(g));
}

// ============================================================
// Kernel 1: dynamic position-bias MLP (729 rows, tiny)
// ============================================================
__device__ __forceinline__ void ln_relu8(float* x, const float* g, const float* b) {
    float mu = 0.f;
#pragma unroll
    for (int d = 0; d < 8; d++) mu += x[d];
    mu *= 0.125f;
    float var = 0.f;
#pragma unroll
    for (int d = 0; d < 8; d++) { float t = x[d] - mu; var += t * t; }
    var *= 0.125f;
    float inv = rsqrtf(var + 1e-5f);
#pragma unroll
    for (int d = 0; d < 8; d++) {
        float t = (x[d] - mu) * inv * g[d] + b[d];
        x[d] = t > 0.f ? t : 0.f;
    }
}

__global__ void pos_mlp_kernel(
    const float* __restrict__ pp_w, const float* __restrict__ pp_b,
    const float* __restrict__ ln1_g, const float* __restrict__ ln1_b,
    const float* __restrict__ l1_w,  const float* __restrict__ l1_b,
    const float* __restrict__ ln2_g, const float* __restrict__ ln2_b,
    const float* __restrict__ l2_w,  const float* __restrict__ l2_b,
    const float* __restrict__ ln3_g, const float* __restrict__ ln3_b,
    const float* __restrict__ l3_w,  const float* __restrict__ l3_b)
{
    int m = blockIdx.x * blockDim.x + threadIdx.x;
    if (m >= TAB) return;
    float bi = (float)(m / 27 - 13);
    float bj = (float)(m % 27 - 13);
    float h[8], t[8];
#pragma unroll
    for (int d = 0; d < 8; d++) h[d] = bi * pp_w[d] + bj * pp_w[8 + d] + pp_b[d];
    ln_relu8(h, ln1_g, ln1_b);
#pragma unroll
    for (int j = 0; j < 8; j++) {
        float a = l1_b[j];
#pragma unroll
        for (int d = 0; d < 8; d++) a += h[d] * l1_w[d * 8 + j];
        t[j] = a;
    }
    ln_relu8(t, ln2_g, ln2_b);
#pragma unroll
    for (int j = 0; j < 8; j++) {
        float a = l2_b[j];
#pragma unroll
        for (int d = 0; d < 8; d++) a += t[d] * l2_w[d * 8 + j];
        h[j] = a;
    }
    ln_relu8(h, ln3_g, ln3_b);
#pragma unroll
    for (int j = 0; j < NH; j++) {
        float a = l3_b[j];
#pragma unroll
        for (int d = 0; d < 8; d++) a += h[d] * l3_w[d * NH + j];
        g_pos[m * NH + j] = a;
    }
}

// ============================================================
// Kernel 1b: expand rpb table -> full bias matrix per head
// ============================================================
__global__ __launch_bounds__(256) void bias_prep_kernel()
{
    int idx = blockIdx.x * 256 + threadIdx.x;
    if (idx >= NH * NQ * NCP) return;
    int c = idx % NCP;
    int q = (idx / NCP) % NQ;
    int h = idx / (NCP * NQ);
    float v = -1e30f;
    if (c < NQ) {
        int qi = q / GS, qj = q - qi * GS;
        int ki = c / GS, kj = c - ki * GS;
        int t = (qi - ki + GS - 1) * 27 + (qj - kj + GS - 1);
        v = g_pos[t * NH + h];
    }
    g_bias[idx] = v;
}

// ============================================================
// Kernel: weight prep — transpose to [n][k], bf16 hi/lo split
// ============================================================
__global__ __launch_bounds__(256) void wprep_kernel(
    const float* __restrict__ wq, const float* __restrict__ wkv,
    const float* __restrict__ wproj)
{
    int idx = blockIdx.x * 256 + threadIdx.x;
    if (idx < KVN * CDIM) {
        int n = idx >> 7, k = idx & 127;
        float v = (n < 128) ? wq[k * 128 + n] : wkv[k * 256 + (n - 128)];
        __nv_bfloat16 h = __float2bfloat16(v);
        g_wqkv_h[idx] = h;
        g_wqkv_l[idx] = __float2bfloat16(v - __bfloat162float(h));
    } else if (idx < KVN * CDIM + CDIM * CDIM) {
        int j = idx - KVN * CDIM;
        int n = j >> 7, k = j & 127;
        float v = wproj[k * 128 + n];
        __nv_bfloat16 h = __float2bfloat16(v);
        g_wp_h[j] = h;
        g_wp_l[j] = __float2bfloat16(v - __bfloat162float(h));
    }
}

// ============================================================
// Kernel: HMMA GEMM, 3-term split, m64 CTA tiles,
//   32-row B chunks cp.async double-buffered
//   smem 64KB -> 3 CTAs/SM
// ============================================================
#define SM_AH 0
#define SM_AL 16384
#define SM_B  32768            // 2 buffers x 16KB (hi @ +0, lo @ +8192)
#define GSMEM 65536

__global__ __launch_bounds__(256, 3) void hmma_gemm_kernel(
    int mode, const float* __restrict__ Ain,
    float* __restrict__ Cout, const float* __restrict__ bias)
{
    extern __shared__ char smc[];
    const uint32_t sb = smem_u32(smc);
    const int tid = threadIdx.x;
    const int w = tid >> 5, lane = tid & 31;
    const int m0 = blockIdx.x * 64;

    const float* A = (mode == 0) ? Ain : g_att;
    float* C = (mode == 0) ? g_qkv : Cout;
    const __nv_bfloat16* Bh = (mode == 0) ? g_wqkv_h : g_wp_h;
    const __nv_bfloat16* Bl = (mode == 0) ? g_wqkv_l : g_wp_l;
    const int NCH = (mode == 0) ? 12 : 4;     // 32-row B chunks
    const int ldc = (mode == 0) ? KVN : CDIM;
    const bool has_bias = (mode == 1);

    // ---- stage A: 64 rows fp32 -> bf16 hi/lo, swizzled smem ----
    for (int idx = tid; idx < 1024; idx += 256) {
        int row = idx >> 4, c = idx & 15;
        const float* src = A + (size_t)(m0 + row) * CDIM + c * 8;
        float4 v0 = *(const float4*)src;
        float4 v1 = *(const float4*)(src + 4);
        float f[8] = {v0.x, v0.y, v0.z, v0.w, v1.x, v1.y, v1.z, v1.w};
        uint32_t hp[4], lp[4];
#pragma unroll
        for (int q = 0; q < 4; q++)
            split2(f[2 * q], f[2 * q + 1], hp[q], lp[q]);
        uint32_t off = swz(row, c);
        *(uint4*)(smc + SM_AH + off) = make_uint4(hp[0], hp[1], hp[2], hp[3]);
        *(uint4*)(smc + SM_AL + off) = make_uint4(lp[0], lp[1], lp[2], lp[3]);
    }

    // prefetch B chunk 0
    {
        for (int idx = tid; idx < 512; idx += 256) {
            int row = idx >> 4, c = idx & 15;
            uint32_t dst = sb + SM_B + swz(row, c);
            const size_t gi = (size_t)row * CDIM + c * 8;
            cpasync16(dst, Bh + gi);
            cpasync16(dst + 8192, Bl + gi);
        }
        asm volatile("cp.async.commit_group;");
    }

    const int wm = w >> 1;        // 0..3 -> 16 m-rows
    const int wn = w & 1;         // 0..1 -> 16 n-cols of the 32-col chunk
    const int lrow = lane & 15;
    const int lchunk = lane >> 4;

    for (int ch = 0; ch < NCH; ch++) {
        const int n0 = ch * 32;
        if (ch + 1 < NCH) {
            for (int idx = tid; idx < 512; idx += 256) {
                int row = idx >> 4, c = idx & 15;
                uint32_t dst = sb + SM_B + ((ch + 1) & 1) * 16384 + swz(row, c);
                const size_t gi = (size_t)(n0 + 32 + row) * CDIM + c * 8;
                cpasync16(dst, Bh + gi);
                cpasync16(dst + 8192, Bl + gi);
            }
            asm volatile("cp.async.commit_group;");
            asm volatile("cp.async.wait_group 1;");
        } else {
            asm volatile("cp.async.wait_group 0;");
        }
        __syncthreads();

        const uint32_t bb = sb + SM_B + (ch & 1) * 16384;

        float d[2][4];
#pragma unroll
        for (int ni = 0; ni < 2; ni++)
#pragma unroll
            for (int q = 0; q < 4; q++) d[ni][q] = 0.f;

#pragma unroll
        for (int ks = 0; ks < 8; ks++) {
            const int chunk = ks * 2 + lchunk;
            uint32_t ah[4], al[4];
            int arow = wm * 16 + lrow;
            ldsm_x4(ah[0], ah[1], ah[2], ah[3], sb + SM_AH + swz(arow, chunk));
            ldsm_x4(al[0], al[1], al[2], al[3], sb + SM_AL + swz(arow, chunk));

            int brow = wn * 16 + lrow;
            uint32_t r0, r1, r2, r3;
            ldsm_x4(r0, r1, r2, r3, bb + swz(brow, chunk));
            {
                uint32_t b0[2] = {r0, r2}, b1[2] = {r1, r3};
                mma16816(d[0], ah, b0);
                mma16816(d[1], ah, b1);
                mma16816(d[0], al, b0);
                mma16816(d[1], al, b1);
            }
            ldsm_x4(r0, r1, r2, r3, bb + 8192 + swz(brow, chunk));
            {
                uint32_t b0[2] = {r0, r2}, b1[2] = {r1, r3};
                mma16816(d[0], ah, b0);
                mma16816(d[1], ah, b1);
            }
        }
        __syncthreads();   // compute done before next prefetch overwrites buffer

        const int mrow = m0 + wm * 16 + (lane >> 2);
        const int ncol = n0 + wn * 16 + (lane & 3) * 2;
#pragma unroll
        for (int ni = 0; ni < 2; ni++) {
            float b0 = 0.f, b1 = 0.f;
            if (has_bias) {
                b0 = bias[ncol + ni * 8];
                b1 = bias[ncol + ni * 8 + 1];
            }
            float* p0 = C + (size_t)mrow * ldc + ncol + ni * 8;
            float* p1 = C + (size_t)(mrow + 8) * ldc + ncol + ni * 8;
            *(float2*)p0 = make_float2(d[ni][0] + b0, d[ni][1] + b1);
            *(float2*)p1 = make_float2(d[ni][2] + b0, d[ni][3] + b1);
        }
    }
}

// ============================================================
// HMMA flash attention (fp16, R9-proven): one CTA per (b,h), 8 warps
// ============================================================
#define AQH 0
#define AQL 16640
#define AKH 33280
#define AKL 49920
#define AVTH 66560
#define ATTN_SMEM 80384

template<int NSTART, int NT>
__device__ __forceinline__ void half_pass(
    uint32_t qh, uint32_t ql, uint32_t kh, uint32_t kl, uint32_t vth,
    const float* __restrict__ bias0, const float* __restrict__ bias1,
    int m0, int lane,
    float o[4][4], float& mo0, float& mo1, float& sum0, float& sum1)
{
    const int lrow = lane & 15, lhalf = lane >> 4;
    float S[NT][4];
#pragma unroll
    for (int j = 0; j < NT; j++)
#pragma unroll
        for (int q = 0; q < 4; q++) S[j][q] = 0.f;

    // ---- QK^T, 3 split terms (fp16) ----
#pragma unroll
    for (int term = 0; term < 3; term++) {
        uint32_t Ab = (term == 1) ? ql : qh;
        uint32_t Bb = (term == 2) ? kl : kh;
#pragma unroll
        for (int k0 = 0; k0 < 2; k0++) {
            uint32_t a[4];
            ldsm_x4(a[0], a[1], a[2], a[3],
                    Ab + (uint32_t)((m0 + lrow) * 80 + (k0 * 2 + lhalf) * 16));
#pragma unroll
            for (int np = 0; np < NT / 2; np++) {
                uint32_t r0, r1, r2, r3;
                ldsm_x4(r0, r1, r2, r3,
                        Bb + (uint32_t)(((NSTART + 2 * np) * 8 + lrow) * 80
                                        + (k0 * 2 + lhalf) * 16));
                uint32_t b0[2] = {r0, r2}, b1[2] = {r1, r3};
                mma16816h(S[2 * np], a, b0);
                mma16816h(S[2 * np + 1], a, b1);
            }
        }
    }

    // ---- bias (mask pre-folded) + row max ----
    float ml0 = -1e30f, ml1 = -1e30f;
#pragma unroll
    for (int j = 0; j < NT; j++) {
        float2 v0 = *(const float2*)(bias0 + NSTART * 8 + j * 8);
        float2 v1 = *(const float2*)(bias1 + NSTART * 8 + j * 8);
        S[j][0] += v0.x; S[j][1] += v0.y;
        S[j][2] += v1.x; S[j][3] += v1.y;
        ml0 = fmaxf(ml0, fmaxf(S[j][0], S[j][1]));
        ml1 = fmaxf(ml1, fmaxf(S[j][2], S[j][3]));
    }
    ml0 = fmaxf(ml0, __shfl_xor_sync(0xffffffffu, ml0, 1));
    ml0 = fmaxf(ml0, __shfl_xor_sync(0xffffffffu, ml0, 2));
    ml1 = fmaxf(ml1, __shfl_xor_sync(0xffffffffu, ml1, 1));
    ml1 = fmaxf(ml1, __shfl_xor_sync(0xffffffffu, ml1, 2));
    float mn0 = fmaxf(mo0, ml0), mn1 = fmaxf(mo1, ml1);
    float f0 = __expf(mo0 - mn0), f1 = __expf(mo1 - mn1);
    mo0 = mn0; mo1 = mn1;
    sum0 *= f0; sum1 *= f1;
#pragma unroll
    for (int n = 0; n < 4; n++) {
        o[n][0] *= f0; o[n][1] *= f0;
        o[n][2] *= f1; o[n][3] *= f1;
    }

    // ---- P = exp(S-m) -> fp16 frags; PV single term ----
#pragma unroll
    for (int t = 0; t < NT / 2; t++) {
        uint32_t ah[4];
#pragma unroll
        for (int jj = 0; jj < 2; jj++) {
            int j = 2 * t + jj;
            float p0 = __expf(S[j][0] - mn0);
            float p1 = __expf(S[j][1] - mn0);
            float p2 = __expf(S[j][2] - mn1);
            float p3 = __expf(S[j][3] - mn1);
            sum0 += p0 + p1; sum1 += p2 + p3;
            ah[2 * jj]     = pack2h(p0, p1);
            ah[2 * jj + 1] = pack2h(p2, p3);
        }
        int kchunk = NSTART + 2 * t + lhalf;
#pragma unroll
        for (int np = 0; np < 2; np++) {
            uint32_t r0, r1, r2, r3;
            ldsm_x4(r0, r1, r2, r3,
                    vth + (uint32_t)((np * 16 + lrow) * 432 + kchunk * 16));
            uint32_t b0[2] = {r0, r2}, b1[2] = {r1, r3};
            mma16816h(o[2 * np], ah, b0);
            mma16816h(o[2 * np + 1], ah, b1);
        }
    }
}

__global__ __launch_bounds__(256, 2) void fattn_kernel()
{
    extern __shared__ char smb[];
    const uint32_t sb = smem_u32(smb);
    const int b = blockIdx.x, h = blockIdx.y;
    const int tid = threadIdx.x;

    // ---- stage q*scale/k hi/lo + v single (fp16); Vt transposed ----
    const float* base = g_qkv + (size_t)b * NQ * KVN + h * HD;
    for (int idx = tid; idx < 208 * 32; idx += 256) {
        int n = idx >> 5, d = idx & 31;
        float qv = 0.f, kv = 0.f, vv = 0.f;
        if (n < NQ) {
            const float* row = base + (size_t)n * KVN;
            qv = row[d] * SCALE;
            kv = row[128 + d];
            vv = row[256 + d];
        }
        __half qhh = __float2half(qv);
        __half qll = __float2half(qv - __half2float(qhh));
        __half khh = __float2half(kv);
        __half kll = __float2half(kv - __half2float(khh));
        *(__half*)(smb + AQH + n * 80 + d * 2) = qhh;
        *(__half*)(smb + AQL + n * 80 + d * 2) = qll;
        *(__half*)(smb + AKH + n * 80 + d * 2) = khh;
        *(__half*)(smb + AKL + n * 80 + d * 2) = kll;
        *(__half*)(smb + AVTH + d * 432 + n * 2) = __float2half(vv);
    }
    __syncthreads();

    const int w = tid >> 5, lane = tid & 31;
    for (int s = w; s < 13; s += 8) {
        const int m0 = s * 16;
        const int row0 = m0 + (lane >> 2), row1 = row0 + 8;
        const int rc0 = min(row0, NQ - 1), rc1 = min(row1, NQ - 1);
        const float* bias0 = g_bias + ((size_t)h * NQ + rc0) * NCP + (lane & 3) * 2;
        const float* bias1 = g_bias + ((size_t)h * NQ + rc1) * NCP + (lane & 3) * 2;

        float o[4][4];
#pragma unroll
        for (int n = 0; n < 4; n++)
#pragma unroll
            for (int q = 0; q < 4; q++) o[n][q] = 0.f;
        float mo0 = -1e30f, mo1 = -1e30f, sum0 = 0.f, sum1 = 0.f;

        half_pass<0, 14>(sb + AQH, sb + AQL, sb + AKH, sb + AKL, sb + AVTH,
                         bias0, bias1, m0, lane, o, mo0, mo1, sum0, sum1);
        half_pass<14, 12>(sb + AQH, sb + AQL, sb + AKH, sb + AKL, sb + AVTH,
                          bias0, bias1, m0, lane, o, mo0, mo1, sum0, sum1);

        sum0 += __shfl_xor_sync(0xffffffffu, sum0, 1);
        sum0 += __shfl_xor_sync(0xffffffffu, sum0, 2);
        sum1 += __shfl_xor_sync(0xffffffffu, sum1, 1);
        sum1 += __shfl_xor_sync(0xffffffffu, sum1, 2);
        float i0 = 1.f / sum0, i1 = 1.f / sum1;

#pragma unroll
        for (int n = 0; n < 4; n++) {
            int d0 = n * 8 + (lane & 3) * 2;
            if (row0 < NQ)
                *(float2*)&g_att[((size_t)b * NQ + row0) * CDIM + h * HD + d0] =
                    make_float2(o[n][0] * i0, o[n][1] * i0);
            if (row1 < NQ)
                *(float2*)&g_att[((size_t)b * NQ + row1) * CDIM + h * HD + d0] =
                    make_float2(o[n][2] * i1, o[n][3] * i1);
        }
    }
}

// ============================================================
// launch
// ============================================================
extern "C" void kernel_launch(void* const* d_in, const int* in_sizes, int n_in,
                              void* d_out, int out_size)
{
    const float* x     = (const float*)d_in[0];
    const float* wq    = (const float*)d_in[1];
    const float* wkv   = (const float*)d_in[2];
    const float* wproj = (const float*)d_in[3];
    const float* bproj = (const float*)d_in[4];
    const float* pp_w  = (const float*)d_in[5];
    const float* pp_b  = (const float*)d_in[6];
    const float* ln1_g = (const float*)d_in[7];
    const float* ln1_b = (const float*)d_in[8];
    const float* l1_w  = (const float*)d_in[9];
    const float* l1_b  = (const float*)d_in[10];
    const float* ln2_g = (const float*)d_in[11];
    const float* ln2_b = (const float*)d_in[12];
    const float* l2_w  = (const float*)d_in[13];
    const float* l2_b  = (const float*)d_in[14];
    const float* ln3_g = (const float*)d_in[15];
    const float* ln3_b = (const float*)d_in[16];
    const float* l3_w  = (const float*)d_in[17];
    const float* l3_b  = (const float*)d_in[18];
    float* out = (float*)d_out;

    cudaFuncSetAttribute(hmma_gemm_kernel,
                         cudaFuncAttributeMaxDynamicSharedMemorySize, GSMEM);
    cudaFuncSetAttribute(fattn_kernel,
                         cudaFuncAttributeMaxDynamicSharedMemorySize, ATTN_SMEM);

    pos_mlp_kernel<<<3, 256>>>(pp_w, pp_b, ln1_g, ln1_b, l1_w, l1_b,
                               ln2_g, ln2_b, l2_w, l2_b,
                               ln3_g, ln3_b, l3_w, l3_b);

    bias_prep_kernel<<<(NH * NQ * NCP + 255) / 256, 256>>>();

    wprep_kernel<<<256, 256>>>(wq, wkv, wproj);

    // QKV: x @ [wq|wkv] -> g_qkv (fp32)
    hmma_gemm_kernel<<<MTOT / 64, 256, GSMEM>>>(0, x, nullptr, nullptr);

    // flash attention -> g_att (fp32)
    fattn_kernel<<<dim3(BATCH, NH), 256, ATTN_SMEM>>>();

    // Proj: g_att @ wproj + bproj -> out (fp32)
    hmma_gemm_kernel<<<MTOT / 64, 256, GSMEM>>>(1, nullptr, out, bproj);
}

// round 11
// speedup vs baseline: 1.0964x; 1.0964x over previous
#include <cuda_runtime.h>
#include <cuda_bf16.h>
#include <cuda_fp16.h>
#include <math.h>
#include <stdint.h>

#define GS    14
#define NQ    196            // GS*GS
#define CDIM  128
#define NH    4
#define HD    32
#define BATCH 1024
#define MTOT  (BATCH * NQ)   // 200704
#define KVN   384            // q(128) | k(128) | v(128)
#define TAB   729            // (2*GS-1)^2
#define NCP   208            // padded col count
#define SCALE 0.17677669529663688f   // 32^-0.5

// ---- scratch (static device allocations; no cudaMalloc allowed) ----
__device__ float g_qkv[(size_t)MTOT * KVN];   // ~308 MB
__device__ float g_att[(size_t)MTOT * CDIM];  // ~103 MB
__device__ float g_pos[TAB * NH];
__device__ float g_bias[NH * NQ * NCP];       // precomputed rpb, cols padded w/ -1e30
__device__ __half g_wqkv[KVN * CDIM];         // [n=384][k=128] fp16
__device__ __half g_wp[CDIM * CDIM];          // [n=128][k=128] fp16

// ============================================================
// helpers
// ============================================================
__device__ __forceinline__ uint32_t smem_u32(const void* p) {
    uint32_t a;
    asm("{ .reg .u64 t; cvta.to.shared.u64 t, %1; cvt.u32.u64 %0, t; }"
        : "=r"(a) : "l"(p));
    return a;
}
__device__ __forceinline__ void ldsm_x4(uint32_t& r0, uint32_t& r1,
                                        uint32_t& r2, uint32_t& r3, uint32_t addr) {
    asm volatile("ldmatrix.sync.aligned.m8n8.x4.shared.b16 {%0,%1,%2,%3}, [%4];"
                 : "=r"(r0), "=r"(r1), "=r"(r2), "=r"(r3) : "r"(addr));
}
// fp16 mma
__device__ __forceinline__ void mma16816h(float* d, const uint32_t* a, const uint32_t* b) {
    asm volatile("mma.sync.aligned.m16n8k16.row.col.f32.f16.f16.f32 "
                 "{%0,%1,%2,%3}, {%4,%5,%6,%7}, {%8,%9}, {%0,%1,%2,%3};"
                 : "+f"(d[0]), "+f"(d[1]), "+f"(d[2]), "+f"(d[3])
                 : "r"(a[0]), "r"(a[1]), "r"(a[2]), "r"(a[3]),
                   "r"(b[0]), "r"(b[1]));
}
// fp16 hi/lo split of two fp32 values -> packed half2 words
__device__ __forceinline__ void split2h(float v0, float v1, uint32_t& hi, uint32_t& lo) {
    __half h0 = __float2half(v0), h1 = __float2half(v1);
    __half2 H = __halves2half2(h0, h1);
    __half2 L = __halves2half2(__float2half(v0 - __half2float(h0)),
                               __float2half(v1 - __half2float(h1)));
    hi = *(uint32_t*)&H;
    lo = *(uint32_t*)&L;
}
__device__ __forceinline__ uint32_t pack2h(float v0, float v1) {
    __half2 H = __halves2half2(__float2half(v0), __float2half(v1));
    return *(uint32_t*)&H;
}
// swizzled byte offset inside a [rows]x128 16-bit tile (256B rows, 16B chunks)
__device__ __forceinline__ uint32_t swz(int row, int chunk) {
    return (uint32_t)(row * 256 + ((chunk ^ (row & 7)) << 4));
}
__device__ __forceinline__ void cpasync16(uint32_t saddr, const void* g) {
    asm volatile("cp.async.cg.shared.global [%0], [%1], 16;"
                 :: "r"(saddr), "l"(g));
}

// ============================================================
// Kernel 1: dynamic position-bias MLP (729 rows, tiny)
// ============================================================
__device__ __forceinline__ void ln_relu8(float* x, const float* g, const float* b) {
    float mu = 0.f;
#pragma unroll
    for (int d = 0; d < 8; d++) mu += x[d];
    mu *= 0.125f;
    float var = 0.f;
#pragma unroll
    for (int d = 0; d < 8; d++) { float t = x[d] - mu; var += t * t; }
    var *= 0.125f;
    float inv = rsqrtf(var + 1e-5f);
#pragma unroll
    for (int d = 0; d < 8; d++) {
        float t = (x[d] - mu) * inv * g[d] + b[d];
        x[d] = t > 0.f ? t : 0.f;
    }
}

__global__ void pos_mlp_kernel(
    const float* __restrict__ pp_w, const float* __restrict__ pp_b,
    const float* __restrict__ ln1_g, const float* __restrict__ ln1_b,
    const float* __restrict__ l1_w,  const float* __restrict__ l1_b,
    const float* __restrict__ ln2_g, const float* __restrict__ ln2_b,
    const float* __restrict__ l2_w,  const float* __restrict__ l2_b,
    const float* __restrict__ ln3_g, const float* __restrict__ ln3_b,
    const float* __restrict__ l3_w,  const float* __restrict__ l3_b)
{
    int m = blockIdx.x * blockDim.x + threadIdx.x;
    if (m >= TAB) return;
    float bi = (float)(m / 27 - 13);
    float bj = (float)(m % 27 - 13);
    float h[8], t[8];
#pragma unroll
    for (int d = 0; d < 8; d++) h[d] = bi * pp_w[d] + bj * pp_w[8 + d] + pp_b[d];
    ln_relu8(h, ln1_g, ln1_b);
#pragma unroll
    for (int j = 0; j < 8; j++) {
        float a = l1_b[j];
#pragma unroll
        for (int d = 0; d < 8; d++) a += h[d] * l1_w[d * 8 + j];
        t[j] = a;
    }
    ln_relu8(t, ln2_g, ln2_b);
#pragma unroll
    for (int j = 0; j < 8; j++) {
        float a = l2_b[j];
#pragma unroll
        for (int d = 0; d < 8; d++) a += t[d] * l2_w[d * 8 + j];
        h[j] = a;
    }
    ln_relu8(h, ln3_g, ln3_b);
#pragma unroll
    for (int j = 0; j < NH; j++) {
        float a = l3_b[j];
#pragma unroll
        for (int d = 0; d < 8; d++) a += h[d] * l3_w[d * NH + j];
        g_pos[m * NH + j] = a;
    }
}

// ============================================================
// Kernel 1b: expand rpb table -> full bias matrix per head
// ============================================================
__global__ __launch_bounds__(256) void bias_prep_kernel()
{
    int idx = blockIdx.x * 256 + threadIdx.x;
    if (idx >= NH * NQ * NCP) return;
    int c = idx % NCP;
    int q = (idx / NCP) % NQ;
    int h = idx / (NCP * NQ);
    float v = -1e30f;
    if (c < NQ) {
        int qi = q / GS, qj = q - qi * GS;
        int ki = c / GS, kj = c - ki * GS;
        int t = (qi - ki + GS - 1) * 27 + (qj - kj + GS - 1);
        v = g_pos[t * NH + h];
    }
    g_bias[idx] = v;
}

// ============================================================
// Kernel: weight prep — transpose to [n][k], single fp16
// ============================================================
__global__ __launch_bounds__(256) void wprep_kernel(
    const float* __restrict__ wq, const float* __restrict__ wkv,
    const float* __restrict__ wproj)
{
    int idx = blockIdx.x * 256 + threadIdx.x;
    if (idx < KVN * CDIM) {
        int n = idx >> 7, k = idx & 127;
        float v = (n < 128) ? wq[k * 128 + n] : wkv[k * 256 + (n - 128)];
        g_wqkv[idx] = __float2half(v);
    } else if (idx < KVN * CDIM + CDIM * CDIM) {
        int j = idx - KVN * CDIM;
        int n = j >> 7, k = j & 127;
        g_wp[j] = __float2half(wproj[k * 128 + n]);
    }
}

// ============================================================
// Kernel: HMMA GEMM fp16 2-term: D = (Ah + Al) @ Wh^T
//   A fp16 hi/lo (exact to ~2^-22), W single fp16
//   m64 CTA tiles, 32-row B chunks cp.async double-buffered
//   smem 48KB -> 3 CTAs/SM
// ============================================================
#define SM_AH 0
#define SM_AL 16384
#define SM_B  32768            // 2 buffers x 8KB
#define GSMEM 49152

__global__ __launch_bounds__(256, 3) void hmma_gemm_kernel(
    int mode, const float* __restrict__ Ain,
    float* __restrict__ Cout, const float* __restrict__ bias)
{
    extern __shared__ char smc[];
    const uint32_t sb = smem_u32(smc);
    const int tid = threadIdx.x;
    const int w = tid >> 5, lane = tid & 31;
    const int m0 = blockIdx.x * 64;

    const float* A = (mode == 0) ? Ain : g_att;
    float* C = (mode == 0) ? g_qkv : Cout;
    const __half* B = (mode == 0) ? g_wqkv : g_wp;
    const int NCH = (mode == 0) ? 12 : 4;     // 32-row B chunks
    const int ldc = (mode == 0) ? KVN : CDIM;
    const bool has_bias = (mode == 1);

    // ---- stage A: 64 rows fp32 -> fp16 hi/lo, swizzled smem ----
    for (int idx = tid; idx < 1024; idx += 256) {
        int row = idx >> 4, c = idx & 15;
        const float* src = A + (size_t)(m0 + row) * CDIM + c * 8;
        float4 v0 = *(const float4*)src;
        float4 v1 = *(const float4*)(src + 4);
        float f[8] = {v0.x, v0.y, v0.z, v0.w, v1.x, v1.y, v1.z, v1.w};
        uint32_t hp[4], lp[4];
#pragma unroll
        for (int q = 0; q < 4; q++)
            split2h(f[2 * q], f[2 * q + 1], hp[q], lp[q]);
        uint32_t off = swz(row, c);
        *(uint4*)(smc + SM_AH + off) = make_uint4(hp[0], hp[1], hp[2], hp[3]);
        *(uint4*)(smc + SM_AL + off) = make_uint4(lp[0], lp[1], lp[2], lp[3]);
    }

    // prefetch B chunk 0
    {
        for (int idx = tid; idx < 512; idx += 256) {
            int row = idx >> 4, c = idx & 15;
            cpasync16(sb + SM_B + swz(row, c), B + (size_t)row * CDIM + c * 8);
        }
        asm volatile("cp.async.commit_group;");
    }

    const int wm = w >> 1;        // 0..3 -> 16 m-rows
    const int wn = w & 1;         // 0..1 -> 16 n-cols of the 32-col chunk
    const int lrow = lane & 15;
    const int lchunk = lane >> 4;

    for (int ch = 0; ch < NCH; ch++) {
        const int n0 = ch * 32;
        if (ch + 1 < NCH) {
            for (int idx = tid; idx < 512; idx += 256) {
                int row = idx >> 4, c = idx & 15;
                uint32_t dst = sb + SM_B + ((ch + 1) & 1) * 8192 + swz(row, c);
                cpasync16(dst, B + (size_t)(n0 + 32 + row) * CDIM + c * 8);
            }
            asm volatile("cp.async.commit_group;");
            asm volatile("cp.async.wait_group 1;");
        } else {
            asm volatile("cp.async.wait_group 0;");
        }
        __syncthreads();

        const uint32_t bb = sb + SM_B + (ch & 1) * 8192;

        float d[2][4];
#pragma unroll
        for (int ni = 0; ni < 2; ni++)
#pragma unroll
            for (int q = 0; q < 4; q++) d[ni][q] = 0.f;

#pragma unroll
        for (int ks = 0; ks < 8; ks++) {
            const int chunk = ks * 2 + lchunk;
            uint32_t ah[4], al[4];
            int arow = wm * 16 + lrow;
            ldsm_x4(ah[0], ah[1], ah[2], ah[3], sb + SM_AH + swz(arow, chunk));
            ldsm_x4(al[0], al[1], al[2], al[3], sb + SM_AL + swz(arow, chunk));

            int brow = wn * 16 + lrow;
            uint32_t r0, r1, r2, r3;
            ldsm_x4(r0, r1, r2, r3, bb + swz(brow, chunk));
            uint32_t b0[2] = {r0, r2}, b1[2] = {r1, r3};
            mma16816h(d[0], ah, b0);
            mma16816h(d[1], ah, b1);
            mma16816h(d[0], al, b0);
            mma16816h(d[1], al, b1);
        }
        __syncthreads();   // compute done before next prefetch overwrites buffer

        const int mrow = m0 + wm * 16 + (lane >> 2);
        const int ncol = n0 + wn * 16 + (lane & 3) * 2;
#pragma unroll
        for (int ni = 0; ni < 2; ni++) {
            float b0 = 0.f, b1 = 0.f;
            if (has_bias) {
                b0 = bias[ncol + ni * 8];
                b1 = bias[ncol + ni * 8 + 1];
            }
            float* p0 = C + (size_t)mrow * ldc + ncol + ni * 8;
            float* p1 = C + (size_t)(mrow + 8) * ldc + ncol + ni * 8;
            *(float2*)p0 = make_float2(d[ni][0] + b0, d[ni][1] + b1);
            *(float2*)p1 = make_float2(d[ni][2] + b0, d[ni][3] + b1);
        }
    }
}

// ============================================================
// HMMA flash attention (fp16, R9-proven): one CTA per (b,h), 8 warps
//   Q/K hi/lo fp16: [208 rows][32 d], stride 80 B
//   Vt single fp16: [32 d][208 kk], stride 432 B
// ============================================================
#define AQH 0
#define AQL 16640
#define AKH 33280
#define AKL 49920
#define AVTH 66560
#define ATTN_SMEM 80384

template<int NSTART, int NT>
__device__ __forceinline__ void half_pass(
    uint32_t qh, uint32_t ql, uint32_t kh, uint32_t kl, uint32_t vth,
    const float* __restrict__ bias0, const float* __restrict__ bias1,
    int m0, int lane,
    float o[4][4], float& mo0, float& mo1, float& sum0, float& sum1)
{
    const int lrow = lane & 15, lhalf = lane >> 4;
    float S[NT][4];
#pragma unroll
    for (int j = 0; j < NT; j++)
#pragma unroll
        for (int q = 0; q < 4; q++) S[j][q] = 0.f;

    // ---- QK^T, 3 split terms (fp16) ----
#pragma unroll
    for (int term = 0; term < 3; term++) {
        uint32_t Ab = (term == 1) ? ql : qh;
        uint32_t Bb = (term == 2) ? kl : kh;
#pragma unroll
        for (int k0 = 0; k0 < 2; k0++) {
            uint32_t a[4];
            ldsm_x4(a[0], a[1], a[2], a[3],
                    Ab + (uint32_t)((m0 + lrow) * 80 + (k0 * 2 + lhalf) * 16));
#pragma unroll
            for (int np = 0; np < NT / 2; np++) {
                uint32_t r0, r1, r2, r3;
                ldsm_x4(r0, r1, r2, r3,
                        Bb + (uint32_t)(((NSTART + 2 * np) * 8 + lrow) * 80
                                        + (k0 * 2 + lhalf) * 16));
                uint32_t b0[2] = {r0, r2}, b1[2] = {r1, r3};
                mma16816h(S[2 * np], a, b0);
                mma16816h(S[2 * np + 1], a, b1);
            }
        }
    }

    // ---- bias (mask pre-folded) + row max ----
    float ml0 = -1e30f, ml1 = -1e30f;
#pragma unroll
    for (int j = 0; j < NT; j++) {
        float2 v0 = *(const float2*)(bias0 + NSTART * 8 + j * 8);
        float2 v1 = *(const float2*)(bias1 + NSTART * 8 + j * 8);
        S[j][0] += v0.x; S[j][1] += v0.y;
        S[j][2] += v1.x; S[j][3] += v1.y;
        ml0 = fmaxf(ml0, fmaxf(S[j][0], S[j][1]));
        ml1 = fmaxf(ml1, fmaxf(S[j][2], S[j][3]));
    }
    ml0 = fmaxf(ml0, __shfl_xor_sync(0xffffffffu, ml0, 1));
    ml0 = fmaxf(ml0, __shfl_xor_sync(0xffffffffu, ml0, 2));
    ml1 = fmaxf(ml1, __shfl_xor_sync(0xffffffffu, ml1, 1));
    ml1 = fmaxf(ml1, __shfl_xor_sync(0xffffffffu, ml1, 2));
    float mn0 = fmaxf(mo0, ml0), mn1 = fmaxf(mo1, ml1);
    float f0 = __expf(mo0 - mn0), f1 = __expf(mo1 - mn1);
    mo0 = mn0; mo1 = mn1;
    sum0 *= f0; sum1 *= f1;
#pragma unroll
    for (int n = 0; n < 4; n++) {
        o[n][0] *= f0; o[n][1] *= f0;
        o[n][2] *= f1; o[n][3] *= f1;
    }

    // ---- P = exp(S-m) -> fp16 frags; PV single term ----
#pragma unroll
    for (int t = 0; t < NT / 2; t++) {
        uint32_t ah[4];
#pragma unroll
        for (int jj = 0; jj < 2; jj++) {
            int j = 2 * t + jj;
            float p0 = __expf(S[j][0] - mn0);
            float p1 = __expf(S[j][1] - mn0);
            float p2 = __expf(S[j][2] - mn1);
            float p3 = __expf(S[j][3] - mn1);
            sum0 += p0 + p1; sum1 += p2 + p3;
            ah[2 * jj]     = pack2h(p0, p1);
            ah[2 * jj + 1] = pack2h(p2, p3);
        }
        int kchunk = NSTART + 2 * t + lhalf;
#pragma unroll
        for (int np = 0; np < 2; np++) {
            uint32_t r0, r1, r2, r3;
            ldsm_x4(r0, r1, r2, r3,
                    vth + (uint32_t)((np * 16 + lrow) * 432 + kchunk * 16));
            uint32_t b0[2] = {r0, r2}, b1[2] = {r1, r3};
            mma16816h(o[2 * np], ah, b0);
            mma16816h(o[2 * np + 1], ah, b1);
        }
    }
}

__global__ __launch_bounds__(256, 2) void fattn_kernel()
{
    extern __shared__ char smb[];
    const uint32_t sb = smem_u32(smb);
    const int b = blockIdx.x, h = blockIdx.y;
    const int tid = threadIdx.x;

    // ---- stage q*scale/k hi/lo + v single (fp16); Vt transposed ----
    const float* base = g_qkv + (size_t)b * NQ * KVN + h * HD;
    for (int idx = tid; idx < 208 * 32; idx += 256) {
        int n = idx >> 5, d = idx & 31;
        float qv = 0.f, kv = 0.f, vv = 0.f;
        if (n < NQ) {
            const float* row = base + (size_t)n * KVN;
            qv = row[d] * SCALE;
            kv = row[128 + d];
            vv = row[256 + d];
        }
        __half qhh = __float2half(qv);
        __half qll = __float2half(qv - __half2float(qhh));
        __half khh = __float2half(kv);
        __half kll = __float2half(kv - __half2float(khh));
        *(__half*)(smb + AQH + n * 80 + d * 2) = qhh;
        *(__half*)(smb + AQL + n * 80 + d * 2) = qll;
        *(__half*)(smb + AKH + n * 80 + d * 2) = khh;
        *(__half*)(smb + AKL + n * 80 + d * 2) = kll;
        *(__half*)(smb + AVTH + d * 432 + n * 2) = __float2half(vv);
    }
    __syncthreads();

    const int w = tid >> 5, lane = tid & 31;
    for (int s = w; s < 13; s += 8) {
        const int m0 = s * 16;
        const int row0 = m0 + (lane >> 2), row1 = row0 + 8;
        const int rc0 = min(row0, NQ - 1), rc1 = min(row1, NQ - 1);
        const float* bias0 = g_bias + ((size_t)h * NQ + rc0) * NCP + (lane & 3) * 2;
        const float* bias1 = g_bias + ((size_t)h * NQ + rc1) * NCP + (lane & 3) * 2;

        float o[4][4];
#pragma unroll
        for (int n = 0; n < 4; n++)
#pragma unroll
            for (int q = 0; q < 4; q++) o[n][q] = 0.f;
        float mo0 = -1e30f, mo1 = -1e30f, sum0 = 0.f, sum1 = 0.f;

        half_pass<0, 14>(sb + AQH, sb + AQL, sb + AKH, sb + AKL, sb + AVTH,
                         bias0, bias1, m0, lane, o, mo0, mo1, sum0, sum1);
        half_pass<14, 12>(sb + AQH, sb + AQL, sb + AKH, sb + AKL, sb + AVTH,
                          bias0, bias1, m0, lane, o, mo0, mo1, sum0, sum1);

        sum0 += __shfl_xor_sync(0xffffffffu, sum0, 1);
        sum0 += __shfl_xor_sync(0xffffffffu, sum0, 2);
        sum1 += __shfl_xor_sync(0xffffffffu, sum1, 1);
        sum1 += __shfl_xor_sync(0xffffffffu, sum1, 2);
        float i0 = 1.f / sum0, i1 = 1.f / sum1;

#pragma unroll
        for (int n = 0; n < 4; n++) {
            int d0 = n * 8 + (lane & 3) * 2;
            if (row0 < NQ)
                *(float2*)&g_att[((size_t)b * NQ + row0) * CDIM + h * HD + d0] =
                    make_float2(o[n][0] * i0, o[n][1] * i0);
            if (row1 < NQ)
                *(float2*)&g_att[((size_t)b * NQ + row1) * CDIM + h * HD + d0] =
                    make_float2(o[n][2] * i1, o[n][3] * i1);
        }
    }
}

// ============================================================
// launch
// ============================================================
extern "C" void kernel_launch(void* const* d_in, const int* in_sizes, int n_in,
                              void* d_out, int out_size)
{
    const float* x     = (const float*)d_in[0];
    const float* wq    = (const float*)d_in[1];
    const float* wkv   = (const float*)d_in[2];
    const float* wproj = (const float*)d_in[3];
    const float* bproj = (const float*)d_in[4];
    const float* pp_w  = (const float*)d_in[5];
    const float* pp_b  = (const float*)d_in[6];
    const float* ln1_g = (const float*)d_in[7];
    const float* ln1_b = (const float*)d_in[8];
    const float* l1_w  = (const float*)d_in[9];
    const float* l1_b  = (const float*)d_in[10];
    const float* ln2_g = (const float*)d_in[11];
    const float* ln2_b = (const float*)d_in[12];
    const float* l2_w  = (const float*)d_in[13];
    const float* l2_b  = (const float*)d_in[14];
    const float* ln3_g = (const float*)d_in[15];
    const float* ln3_b = (const float*)d_in[16];
    const float* l3_w  = (const float*)d_in[17];
    const float* l3_b  = (const float*)d_in[18];
    float* out = (float*)d_out;

    cudaFuncSetAttribute(hmma_gemm_kernel,
                         cudaFuncAttributeMaxDynamicSharedMemorySize, GSMEM);
    cudaFuncSetAttribute(fattn_kernel,
                         cudaFuncAttributeMaxDynamicSharedMemorySize, ATTN_SMEM);

    pos_mlp_kernel<<<3, 256>>>(pp_w, pp_b, ln1_g, ln1_b, l1_w, l1_b,
                               ln2_g, ln2_b, l2_w, l2_b,
                               ln3_g, ln3_b, l3_w, l3_b);

    bias_prep_kernel<<<(NH * NQ * NCP + 255) / 256, 256>>>();

    wprep_kernel<<<256, 256>>>(wq, wkv, wproj);

    // QKV: x @ [wq|wkv] -> g_qkv (fp32)
    hmma_gemm_kernel<<<MTOT / 64, 256, GSMEM>>>(0, x, nullptr, nullptr);

    // flash attention -> g_att (fp32)
    fattn_kernel<<<dim3(BATCH, NH), 256, ATTN_SMEM>>>();

    // Proj: g_att @ wproj + bproj -> out (fp32)
    hmma_gemm_kernel<<<MTOT / 64, 256, GSMEM>>>(1, nullptr, out, bproj);
}

// round 12
// speedup vs baseline: 1.1694x; 1.0666x over previous
#include <cuda_runtime.h>
#include <cuda_bf16.h>
#include <cuda_fp16.h>
#include <math.h>
#include <stdint.h>

#define GS    14
#define NQ    196            // GS*GS
#define CDIM  128
#define NH    4
#define HD    32
#define BATCH 1024
#define MTOT  (BATCH * NQ)   // 200704
#define KVN   384            // q(128) | k(128) | v(128)
#define TAB   729            // (2*GS-1)^2
#define NCP   208            // padded col count
#define SCALE 0.17677669529663688f   // 32^-0.5

// ---- scratch (static device allocations; no cudaMalloc allowed) ----
__device__ float g_qkv[(size_t)MTOT * KVN];   // ~308 MB
__device__ float g_att[(size_t)MTOT * CDIM];  // ~103 MB
__device__ float g_pos[TAB * NH];
__device__ float g_bias[NH * NQ * NCP];       // precomputed rpb, cols padded w/ -1e30
__device__ __half g_wqkv[KVN * CDIM];         // [n=384][k=128] fp16
__device__ __half g_wp[CDIM * CDIM];          // [n=128][k=128] fp16

// ============================================================
// helpers
// ============================================================
__device__ __forceinline__ uint32_t smem_u32(const void* p) {
    uint32_t a;
    asm("{ .reg .u64 t; cvta.to.shared.u64 t, %1; cvt.u32.u64 %0, t; }"
        : "=r"(a) : "l"(p));
    return a;
}
__device__ __forceinline__ void ldsm_x4(uint32_t& r0, uint32_t& r1,
                                        uint32_t& r2, uint32_t& r3, uint32_t addr) {
    asm volatile("ldmatrix.sync.aligned.m8n8.x4.shared.b16 {%0,%1,%2,%3}, [%4];"
                 : "=r"(r0), "=r"(r1), "=r"(r2), "=r"(r3) : "r"(addr));
}
// fp16 mma
__device__ __forceinline__ void mma16816h(float* d, const uint32_t* a, const uint32_t* b) {
    asm volatile("mma.sync.aligned.m16n8k16.row.col.f32.f16.f16.f32 "
                 "{%0,%1,%2,%3}, {%4,%5,%6,%7}, {%8,%9}, {%0,%1,%2,%3};"
                 : "+f"(d[0]), "+f"(d[1]), "+f"(d[2]), "+f"(d[3])
                 : "r"(a[0]), "r"(a[1]), "r"(a[2]), "r"(a[3]),
                   "r"(b[0]), "r"(b[1]));
}
// fp16 hi/lo split of two fp32 values -> packed half2 words
__device__ __forceinline__ void split2h(float v0, float v1, uint32_t& hi, uint32_t& lo) {
    __half h0 = __float2half(v0), h1 = __float2half(v1);
    __half2 H = __halves2half2(h0, h1);
    __half2 L = __halves2half2(__float2half(v0 - __half2float(h0)),
                               __float2half(v1 - __half2float(h1)));
    hi = *(uint32_t*)&H;
    lo = *(uint32_t*)&L;
}
__device__ __forceinline__ uint32_t pack2h(float v0, float v1) {
    __half2 H = __halves2half2(__float2half(v0), __float2half(v1));
    return *(uint32_t*)&H;
}
// swizzled byte offset inside a [rows]x128 16-bit tile (256B rows, 16B chunks)
__device__ __forceinline__ uint32_t swz(int row, int chunk) {
    return (uint32_t)(row * 256 + ((chunk ^ (row & 7)) << 4));
}
__device__ __forceinline__ void cpasync16(uint32_t saddr, const void* g) {
    asm volatile("cp.async.cg.shared.global [%0], [%1], 16;"
                 :: "r"(saddr), "l"(g));
}

// ============================================================
// Kernel 1: dynamic position-bias MLP (729 rows, tiny)
// ============================================================
__device__ __forceinline__ void ln_relu8(float* x, const float* g, const float* b) {
    float mu = 0.f;
#pragma unroll
    for (int d = 0; d < 8; d++) mu += x[d];
    mu *= 0.125f;
    float var = 0.f;
#pragma unroll
    for (int d = 0; d < 8; d++) { float t = x[d] - mu; var += t * t; }
    var *= 0.125f;
    float inv = rsqrtf(var + 1e-5f);
#pragma unroll
    for (int d = 0; d < 8; d++) {
        float t = (x[d] - mu) * inv * g[d] + b[d];
        x[d] = t > 0.f ? t : 0.f;
    }
}

__global__ void pos_mlp_kernel(
    const float* __restrict__ pp_w, const float* __restrict__ pp_b,
    const float* __restrict__ ln1_g, const float* __restrict__ ln1_b,
    const float* __restrict__ l1_w,  const float* __restrict__ l1_b,
    const float* __restrict__ ln2_g, const float* __restrict__ ln2_b,
    const float* __restrict__ l2_w,  const float* __restrict__ l2_b,
    const float* __restrict__ ln3_g, const float* __restrict__ ln3_b,
    const float* __restrict__ l3_w,  const float* __restrict__ l3_b)
{
    int m = blockIdx.x * blockDim.x + threadIdx.x;
    if (m >= TAB) return;
    float bi = (float)(m / 27 - 13);
    float bj = (float)(m % 27 - 13);
    float h[8], t[8];
#pragma unroll
    for (int d = 0; d < 8; d++) h[d] = bi * pp_w[d] + bj * pp_w[8 + d] + pp_b[d];
    ln_relu8(h, ln1_g, ln1_b);
#pragma unroll
    for (int j = 0; j < 8; j++) {
        float a = l1_b[j];
#pragma unroll
        for (int d = 0; d < 8; d++) a += h[d] * l1_w[d * 8 + j];
        t[j] = a;
    }
    ln_relu8(t, ln2_g, ln2_b);
#pragma unroll
    for (int j = 0; j < 8; j++) {
        float a = l2_b[j];
#pragma unroll
        for (int d = 0; d < 8; d++) a += t[d] * l2_w[d * 8 + j];
        h[j] = a;
    }
    ln_relu8(h, ln3_g, ln3_b);
#pragma unroll
    for (int j = 0; j < NH; j++) {
        float a = l3_b[j];
#pragma unroll
        for (int d = 0; d < 8; d++) a += h[d] * l3_w[d * NH + j];
        g_pos[m * NH + j] = a;
    }
}

// ============================================================
// Kernel 1b: expand rpb table -> full bias matrix per head
// ============================================================
__global__ __launch_bounds__(256) void bias_prep_kernel()
{
    int idx = blockIdx.x * 256 + threadIdx.x;
    if (idx >= NH * NQ * NCP) return;
    int c = idx % NCP;
    int q = (idx / NCP) % NQ;
    int h = idx / (NCP * NQ);
    float v = -1e30f;
    if (c < NQ) {
        int qi = q / GS, qj = q - qi * GS;
        int ki = c / GS, kj = c - ki * GS;
        int t = (qi - ki + GS - 1) * 27 + (qj - kj + GS - 1);
        v = g_pos[t * NH + h];
    }
    g_bias[idx] = v;
}

// ============================================================
// Kernel: weight prep — transpose to [n][k], single fp16
// ============================================================
__global__ __launch_bounds__(256) void wprep_kernel(
    const float* __restrict__ wq, const float* __restrict__ wkv,
    const float* __restrict__ wproj)
{
    int idx = blockIdx.x * 256 + threadIdx.x;
    if (idx < KVN * CDIM) {
        int n = idx >> 7, k = idx & 127;
        float v = (n < 128) ? wq[k * 128 + n] : wkv[k * 256 + (n - 128)];
        g_wqkv[idx] = __float2half(v);
    } else if (idx < KVN * CDIM + CDIM * CDIM) {
        int j = idx - KVN * CDIM;
        int n = j >> 7, k = j & 127;
        g_wp[j] = __float2half(wproj[k * 128 + n]);
    }
}

// ============================================================
// Kernel: HMMA GEMM fp16 2-term: D = (Ah + Al) @ Wh^T
//   m64 CTA, m32n16 warp tiles, 64-row B chunks double-buffered
//   smem 64KB -> 3 CTAs/SM
// ============================================================
#define SM_AH 0
#define SM_AL 16384
#define SM_B  32768            // 2 buffers x 16KB
#define GSMEM 65536

__global__ __launch_bounds__(256, 3) void hmma_gemm_kernel(
    int mode, const float* __restrict__ Ain,
    float* __restrict__ Cout, const float* __restrict__ bias)
{
    extern __shared__ char smc[];
    const uint32_t sb = smem_u32(smc);
    const int tid = threadIdx.x;
    const int w = tid >> 5, lane = tid & 31;
    const int m0 = blockIdx.x * 64;

    const float* A = (mode == 0) ? Ain : g_att;
    float* C = (mode == 0) ? g_qkv : Cout;
    const __half* B = (mode == 0) ? g_wqkv : g_wp;
    const int NCH = (mode == 0) ? 6 : 2;      // 64-row B chunks
    const int ldc = (mode == 0) ? KVN : CDIM;
    const bool has_bias = (mode == 1);

    // ---- stage A: 64 rows fp32 -> fp16 hi/lo, swizzled smem ----
    for (int idx = tid; idx < 1024; idx += 256) {
        int row = idx >> 4, c = idx & 15;
        const float* src = A + (size_t)(m0 + row) * CDIM + c * 8;
        float4 v0 = *(const float4*)src;
        float4 v1 = *(const float4*)(src + 4);
        float f[8] = {v0.x, v0.y, v0.z, v0.w, v1.x, v1.y, v1.z, v1.w};
        uint32_t hp[4], lp[4];
#pragma unroll
        for (int q = 0; q < 4; q++)
            split2h(f[2 * q], f[2 * q + 1], hp[q], lp[q]);
        uint32_t off = swz(row, c);
        *(uint4*)(smc + SM_AH + off) = make_uint4(hp[0], hp[1], hp[2], hp[3]);
        *(uint4*)(smc + SM_AL + off) = make_uint4(lp[0], lp[1], lp[2], lp[3]);
    }

    // prefetch B chunk 0 (64 rows)
    {
        for (int idx = tid; idx < 1024; idx += 256) {
            int row = idx >> 4, c = idx & 15;
            cpasync16(sb + SM_B + swz(row, c), B + (size_t)row * CDIM + c * 8);
        }
        asm volatile("cp.async.commit_group;");
    }

    const int wm = w >> 2;        // 0..1 -> 32 m-rows
    const int wn = w & 3;         // 0..3 -> 16 n-cols of the 64-col chunk
    const int lrow = lane & 15;
    const int lchunk = lane >> 4;

    for (int ch = 0; ch < NCH; ch++) {
        const int n0 = ch * 64;
        if (ch + 1 < NCH) {
            for (int idx = tid; idx < 1024; idx += 256) {
                int row = idx >> 4, c = idx & 15;
                uint32_t dst = sb + SM_B + ((ch + 1) & 1) * 16384 + swz(row, c);
                cpasync16(dst, B + (size_t)(n0 + 64 + row) * CDIM + c * 8);
            }
            asm volatile("cp.async.commit_group;");
            asm volatile("cp.async.wait_group 1;");
        } else {
            asm volatile("cp.async.wait_group 0;");
        }
        __syncthreads();

        const uint32_t bb = sb + SM_B + (ch & 1) * 16384;

        float d[2][2][4];
#pragma unroll
        for (int mi = 0; mi < 2; mi++)
#pragma unroll
            for (int ni = 0; ni < 2; ni++)
#pragma unroll
                for (int q = 0; q < 4; q++) d[mi][ni][q] = 0.f;

#pragma unroll
        for (int ks = 0; ks < 8; ks++) {
            const int chunk = ks * 2 + lchunk;
            uint32_t ah[2][4], al[2][4];
#pragma unroll
            for (int mi = 0; mi < 2; mi++) {
                int arow = wm * 32 + mi * 16 + lrow;
                ldsm_x4(ah[mi][0], ah[mi][1], ah[mi][2], ah[mi][3],
                        sb + SM_AH + swz(arow, chunk));
                ldsm_x4(al[mi][0], al[mi][1], al[mi][2], al[mi][3],
                        sb + SM_AL + swz(arow, chunk));
            }
            int brow = wn * 16 + lrow;
            uint32_t r0, r1, r2, r3;
            ldsm_x4(r0, r1, r2, r3, bb + swz(brow, chunk));
            uint32_t b0[2] = {r0, r2}, b1[2] = {r1, r3};
#pragma unroll
            for (int mi = 0; mi < 2; mi++) {
                mma16816h(d[mi][0], ah[mi], b0);
                mma16816h(d[mi][1], ah[mi], b1);
                mma16816h(d[mi][0], al[mi], b0);
                mma16816h(d[mi][1], al[mi], b1);
            }
        }
        __syncthreads();   // compute done before next prefetch overwrites buffer

#pragma unroll
        for (int mi = 0; mi < 2; mi++) {
            const int mrow = m0 + wm * 32 + mi * 16 + (lane >> 2);
            const int ncol = n0 + wn * 16 + (lane & 3) * 2;
#pragma unroll
            for (int ni = 0; ni < 2; ni++) {
                float b0 = 0.f, b1 = 0.f;
                if (has_bias) {
                    b0 = bias[ncol + ni * 8];
                    b1 = bias[ncol + ni * 8 + 1];
                }
                float* p0 = C + (size_t)mrow * ldc + ncol + ni * 8;
                float* p1 = C + (size_t)(mrow + 8) * ldc + ncol + ni * 8;
                *(float2*)p0 = make_float2(d[mi][ni][0] + b0, d[mi][ni][1] + b1);
                *(float2*)p1 = make_float2(d[mi][ni][2] + b0, d[mi][ni][3] + b1);
            }
        }
    }
}

// ============================================================
// HMMA flash attention (fp16): one CTA per (b,h), 8 warps
//   Q hi/lo fp16: [208 rows][32 d], stride 80 B
//   K single fp16 (2-term QKT: QhKh + QlKh)
//   Vt single fp16: [32 d][208 kk], stride 432 B
// ============================================================
#define AQH 0
#define AQL 16640
#define AKH 33280
#define AVTH 49920
#define ATTN_SMEM 63744

template<int NSTART, int NT>
__device__ __forceinline__ void half_pass(
    uint32_t qh, uint32_t ql, uint32_t kh, uint32_t vth,
    const float* __restrict__ bias0, const float* __restrict__ bias1,
    int m0, int lane,
    float o[4][4], float& mo0, float& mo1, float& sum0, float& sum1)
{
    const int lrow = lane & 15, lhalf = lane >> 4;
    float S[NT][4];
#pragma unroll
    for (int j = 0; j < NT; j++)
#pragma unroll
        for (int q = 0; q < 4; q++) S[j][q] = 0.f;

    // ---- QK^T: QhKh + QlKh (K single; Kh frag shared by both terms) ----
#pragma unroll
    for (int k0 = 0; k0 < 2; k0++) {
        uint32_t aoff = (uint32_t)((m0 + lrow) * 80 + (k0 * 2 + lhalf) * 16);
        uint32_t a_h[4], a_l[4];
        ldsm_x4(a_h[0], a_h[1], a_h[2], a_h[3], qh + aoff);
        ldsm_x4(a_l[0], a_l[1], a_l[2], a_l[3], ql + aoff);
#pragma unroll
        for (int np = 0; np < NT / 2; np++) {
            uint32_t r0, r1, r2, r3;
            ldsm_x4(r0, r1, r2, r3,
                    kh + (uint32_t)(((NSTART + 2 * np) * 8 + lrow) * 80
                                    + (k0 * 2 + lhalf) * 16));
            uint32_t b0[2] = {r0, r2}, b1[2] = {r1, r3};
            mma16816h(S[2 * np], a_h, b0);
            mma16816h(S[2 * np + 1], a_h, b1);
            mma16816h(S[2 * np], a_l, b0);
            mma16816h(S[2 * np + 1], a_l, b1);
        }
    }

    // ---- bias (mask pre-folded) + row max ----
    float ml0 = -1e30f, ml1 = -1e30f;
#pragma unroll
    for (int j = 0; j < NT; j++) {
        float2 v0 = *(const float2*)(bias0 + NSTART * 8 + j * 8);
        float2 v1 = *(const float2*)(bias1 + NSTART * 8 + j * 8);
        S[j][0] += v0.x; S[j][1] += v0.y;
        S[j][2] += v1.x; S[j][3] += v1.y;
        ml0 = fmaxf(ml0, fmaxf(S[j][0], S[j][1]));
        ml1 = fmaxf(ml1, fmaxf(S[j][2], S[j][3]));
    }
    ml0 = fmaxf(ml0, __shfl_xor_sync(0xffffffffu, ml0, 1));
    ml0 = fmaxf(ml0, __shfl_xor_sync(0xffffffffu, ml0, 2));
    ml1 = fmaxf(ml1, __shfl_xor_sync(0xffffffffu, ml1, 1));
    ml1 = fmaxf(ml1, __shfl_xor_sync(0xffffffffu, ml1, 2));
    float mn0 = fmaxf(mo0, ml0), mn1 = fmaxf(mo1, ml1);
    float f0 = __expf(mo0 - mn0), f1 = __expf(mo1 - mn1);
    mo0 = mn0; mo1 = mn1;
    sum0 *= f0; sum1 *= f1;
#pragma unroll
    for (int n = 0; n < 4; n++) {
        o[n][0] *= f0; o[n][1] *= f0;
        o[n][2] *= f1; o[n][3] *= f1;
    }

    // ---- P = exp(S-m) -> fp16 frags; PV single term ----
#pragma unroll
    for (int t = 0; t < NT / 2; t++) {
        uint32_t ah[4];
#pragma unroll
        for (int jj = 0; jj < 2; jj++) {
            int j = 2 * t + jj;
            float p0 = __expf(S[j][0] - mn0);
            float p1 = __expf(S[j][1] - mn0);
            float p2 = __expf(S[j][2] - mn1);
            float p3 = __expf(S[j][3] - mn1);
            sum0 += p0 + p1; sum1 += p2 + p3;
            ah[2 * jj]     = pack2h(p0, p1);
            ah[2 * jj + 1] = pack2h(p2, p3);
        }
        int kchunk = NSTART + 2 * t + lhalf;
#pragma unroll
        for (int np = 0; np < 2; np++) {
            uint32_t r0, r1, r2, r3;
            ldsm_x4(r0, r1, r2, r3,
                    vth + (uint32_t)((np * 16 + lrow) * 432 + kchunk * 16));
            uint32_t b0[2] = {r0, r2}, b1[2] = {r1, r3};
            mma16816h(o[2 * np], ah, b0);
            mma16816h(o[2 * np + 1], ah, b1);
        }
    }
}

__global__ __launch_bounds__(256, 2) void fattn_kernel()
{
    extern __shared__ char smb[];
    const uint32_t sb = smem_u32(smb);
    const int b = blockIdx.x, h = blockIdx.y;
    const int tid = threadIdx.x;

    // ---- stage q*scale hi/lo, k single, v single (fp16, Vt transposed) ----
    const float* base = g_qkv + (size_t)b * NQ * KVN + h * HD;
    for (int idx = tid; idx < 208 * 32; idx += 256) {
        int n = idx >> 5, d = idx & 31;
        float qv = 0.f, kv = 0.f, vv = 0.f;
        if (n < NQ) {
            const float* row = base + (size_t)n * KVN;
            qv = row[d] * SCALE;
            kv = row[128 + d];
            vv = row[256 + d];
        }
        __half qhh = __float2half(qv);
        __half qll = __float2half(qv - __half2float(qhh));
        *(__half*)(smb + AQH + n * 80 + d * 2) = qhh;
        *(__half*)(smb + AQL + n * 80 + d * 2) = qll;
        *(__half*)(smb + AKH + n * 80 + d * 2) = __float2half(kv);
        *(__half*)(smb + AVTH + d * 432 + n * 2) = __float2half(vv);
    }
    __syncthreads();

    const int w = tid >> 5, lane = tid & 31;
    for (int s = w; s < 13; s += 8) {
        const int m0 = s * 16;
        const int row0 = m0 + (lane >> 2), row1 = row0 + 8;
        const int rc0 = min(row0, NQ - 1), rc1 = min(row1, NQ - 1);
        const float* bias0 = g_bias + ((size_t)h * NQ + rc0) * NCP + (lane & 3) * 2;
        const float* bias1 = g_bias + ((size_t)h * NQ + rc1) * NCP + (lane & 3) * 2;

        float o[4][4];
#pragma unroll
        for (int n = 0; n < 4; n++)
#pragma unroll
            for (int q = 0; q < 4; q++) o[n][q] = 0.f;
        float mo0 = -1e30f, mo1 = -1e30f, sum0 = 0.f, sum1 = 0.f;

        half_pass<0, 14>(sb + AQH, sb + AQL, sb + AKH, sb + AVTH,
                         bias0, bias1, m0, lane, o, mo0, mo1, sum0, sum1);
        half_pass<14, 12>(sb + AQH, sb + AQL, sb + AKH, sb + AVTH,
                          bias0, bias1, m0, lane, o, mo0, mo1, sum0, sum1);

        sum0 += __shfl_xor_sync(0xffffffffu, sum0, 1);
        sum0 += __shfl_xor_sync(0xffffffffu, sum0, 2);
        sum1 += __shfl_xor_sync(0xffffffffu, sum1, 1);
        sum1 += __shfl_xor_sync(0xffffffffu, sum1, 2);
        float i0 = 1.f / sum0, i1 = 1.f / sum1;

#pragma unroll
        for (int n = 0; n < 4; n++) {
            int d0 = n * 8 + (lane & 3) * 2;
            if (row0 < NQ)
                *(float2*)&g_att[((size_t)b * NQ + row0) * CDIM + h * HD + d0] =
                    make_float2(o[n][0] * i0, o[n][1] * i0);
            if (row1 < NQ)
                *(float2*)&g_att[((size_t)b * NQ + row1) * CDIM + h * HD + d0] =
                    make_float2(o[n][2] * i1, o[n][3] * i1);
        }
    }
}

// ============================================================
// launch
// ============================================================
extern "C" void kernel_launch(void* const* d_in, const int* in_sizes, int n_in,
                              void* d_out, int out_size)
{
    const float* x     = (const float*)d_in[0];
    const float* wq    = (const float*)d_in[1];
    const float* wkv   = (const float*)d_in[2];
    const float* wproj = (const float*)d_in[3];
    const float* bproj = (const float*)d_in[4];
    const float* pp_w  = (const float*)d_in[5];
    const float* pp_b  = (const float*)d_in[6];
    const float* ln1_g = (const float*)d_in[7];
    const float* ln1_b = (const float*)d_in[8];
    const float* l1_w  = (const float*)d_in[9];
    const float* l1_b  = (const float*)d_in[10];
    const float* ln2_g = (const float*)d_in[11];
    const float* ln2_b = (const float*)d_in[12];
    const float* l2_w  = (const float*)d_in[13];
    const float* l2_b  = (const float*)d_in[14];
    const float* ln3_g = (const float*)d_in[15];
    const float* ln3_b = (const float*)d_in[16];
    const float* l3_w  = (const float*)d_in[17];
    const float* l3_b  = (const float*)d_in[18];
    float* out = (float*)d_out;

    cudaFuncSetAttribute(hmma_gemm_kernel,
                         cudaFuncAttributeMaxDynamicSharedMemorySize, GSMEM);
    cudaFuncSetAttribute(fattn_kernel,
                         cudaFuncAttributeMaxDynamicSharedMemorySize, ATTN_SMEM);

    pos_mlp_kernel<<<3, 256>>>(pp_w, pp_b, ln1_g, ln1_b, l1_w, l1_b,
                               ln2_g, ln2_b, l2_w, l2_b,
                               ln3_g, ln3_b, l3_w, l3_b);

    bias_prep_kernel<<<(NH * NQ * NCP + 255) / 256, 256>>>();

    wprep_kernel<<<256, 256>>>(wq, wkv, wproj);

    // QKV: x @ [wq|wkv] -> g_qkv (fp32)
    hmma_gemm_kernel<<<MTOT / 64, 256, GSMEM>>>(0, x, nullptr, nullptr);

    // flash attention -> g_att (fp32)
    fattn_kernel<<<dim3(BATCH, NH), 256, ATTN_SMEM>>>();

    // Proj: g_att @ wproj + bproj -> out (fp32)
    hmma_gemm_kernel<<<MTOT / 64, 256, GSMEM>>>(1, nullptr, out, bproj);
}

// round 13
// speedup vs baseline: 1.2573x; 1.0752x over previous
#include <cuda_runtime.h>
#include <cuda_bf16.h>
#include <cuda_fp16.h>
#include <math.h>
#include <stdint.h>

#define GS    14
#define NQ    196            // GS*GS
#define CDIM  128
#define NH    4
#define HD    32
#define BATCH 1024
#define MTOT  (BATCH * NQ)   // 200704
#define KVN   384            // q(128) | k(128) | v(128)
#define TAB   729            // (2*GS-1)^2
#define NCP   208            // padded col count
#define SCALE 0.17677669529663688f   // 32^-0.5

// ---- scratch (static device allocations; no cudaMalloc allowed) ----
__device__ float g_qkv[(size_t)MTOT * KVN];   // ~308 MB
__device__ __half g_atth[(size_t)MTOT * CDIM]; // attention out, fp16 (~51 MB)
__device__ float g_pos[TAB * NH];
__device__ float g_bias[NH * NQ * NCP];       // precomputed rpb, cols padded w/ -1e30
__device__ __half g_wqkv[KVN * CDIM];         // [n=384][k=128] fp16
__device__ __half g_wp[CDIM * CDIM];          // [n=128][k=128] fp16

// ============================================================
// helpers
// ============================================================
__device__ __forceinline__ uint32_t smem_u32(const void* p) {
    uint32_t a;
    asm("{ .reg .u64 t; cvta.to.shared.u64 t, %1; cvt.u32.u64 %0, t; }"
        : "=r"(a) : "l"(p));
    return a;
}
__device__ __forceinline__ void ldsm_x4(uint32_t& r0, uint32_t& r1,
                                        uint32_t& r2, uint32_t& r3, uint32_t addr) {
    asm volatile("ldmatrix.sync.aligned.m8n8.x4.shared.b16 {%0,%1,%2,%3}, [%4];"
                 : "=r"(r0), "=r"(r1), "=r"(r2), "=r"(r3) : "r"(addr));
}
// fp16 mma
__device__ __forceinline__ void mma16816h(float* d, const uint32_t* a, const uint32_t* b) {
    asm volatile("mma.sync.aligned.m16n8k16.row.col.f32.f16.f16.f32 "
                 "{%0,%1,%2,%3}, {%4,%5,%6,%7}, {%8,%9}, {%0,%1,%2,%3};"
                 : "+f"(d[0]), "+f"(d[1]), "+f"(d[2]), "+f"(d[3])
                 : "r"(a[0]), "r"(a[1]), "r"(a[2]), "r"(a[3]),
                   "r"(b[0]), "r"(b[1]));
}
// fp16 hi/lo split of two fp32 values -> packed half2 words
__device__ __forceinline__ void split2h(float v0, float v1, uint32_t& hi, uint32_t& lo) {
    __half h0 = __float2half(v0), h1 = __float2half(v1);
    __half2 H = __halves2half2(h0, h1);
    __half2 L = __halves2half2(__float2half(v0 - __half2float(h0)),
                               __float2half(v1 - __half2float(h1)));
    hi = *(uint32_t*)&H;
    lo = *(uint32_t*)&L;
}
__device__ __forceinline__ uint32_t pack2h(float v0, float v1) {
    __half2 H = __halves2half2(__float2half(v0), __float2half(v1));
    return *(uint32_t*)&H;
}
// swizzled byte offset inside a [rows]x128 16-bit tile (256B rows, 16B chunks)
__device__ __forceinline__ uint32_t swz(int row, int chunk) {
    return (uint32_t)(row * 256 + ((chunk ^ (row & 7)) << 4));
}
__device__ __forceinline__ void cpasync16(uint32_t saddr, const void* g) {
    asm volatile("cp.async.cg.shared.global [%0], [%1], 16;"
                 :: "r"(saddr), "l"(g));
}

// ============================================================
// Kernel 1: dynamic position-bias MLP (729 rows, tiny)
// ============================================================
__device__ __forceinline__ void ln_relu8(float* x, const float* g, const float* b) {
    float mu = 0.f;
#pragma unroll
    for (int d = 0; d < 8; d++) mu += x[d];
    mu *= 0.125f;
    float var = 0.f;
#pragma unroll
    for (int d = 0; d < 8; d++) { float t = x[d] - mu; var += t * t; }
    var *= 0.125f;
    float inv = rsqrtf(var + 1e-5f);
#pragma unroll
    for (int d = 0; d < 8; d++) {
        float t = (x[d] - mu) * inv * g[d] + b[d];
        x[d] = t > 0.f ? t : 0.f;
    }
}

__global__ void pos_mlp_kernel(
    const float* __restrict__ pp_w, const float* __restrict__ pp_b,
    const float* __restrict__ ln1_g, const float* __restrict__ ln1_b,
    const float* __restrict__ l1_w,  const float* __restrict__ l1_b,
    const float* __restrict__ ln2_g, const float* __restrict__ ln2_b,
    const float* __restrict__ l2_w,  const float* __restrict__ l2_b,
    const float* __restrict__ ln3_g, const float* __restrict__ ln3_b,
    const float* __restrict__ l3_w,  const float* __restrict__ l3_b)
{
    int m = blockIdx.x * blockDim.x + threadIdx.x;
    if (m >= TAB) return;
    float bi = (float)(m / 27 - 13);
    float bj = (float)(m % 27 - 13);
    float h[8], t[8];
#pragma unroll
    for (int d = 0; d < 8; d++) h[d] = bi * pp_w[d] + bj * pp_w[8 + d] + pp_b[d];
    ln_relu8(h, ln1_g, ln1_b);
#pragma unroll
    for (int j = 0; j < 8; j++) {
        float a = l1_b[j];
#pragma unroll
        for (int d = 0; d < 8; d++) a += h[d] * l1_w[d * 8 + j];
        t[j] = a;
    }
    ln_relu8(t, ln2_g, ln2_b);
#pragma unroll
    for (int j = 0; j < 8; j++) {
        float a = l2_b[j];
#pragma unroll
        for (int d = 0; d < 8; d++) a += t[d] * l2_w[d * 8 + j];
        h[j] = a;
    }
    ln_relu8(h, ln3_g, ln3_b);
#pragma unroll
    for (int j = 0; j < NH; j++) {
        float a = l3_b[j];
#pragma unroll
        for (int d = 0; d < 8; d++) a += h[d] * l3_w[d * NH + j];
        g_pos[m * NH + j] = a;
    }
}

// ============================================================
// Kernel 1b: expand rpb table -> full bias matrix per head
// ============================================================
__global__ __launch_bounds__(256) void bias_prep_kernel()
{
    int idx = blockIdx.x * 256 + threadIdx.x;
    if (idx >= NH * NQ * NCP) return;
    int c = idx % NCP;
    int q = (idx / NCP) % NQ;
    int h = idx / (NCP * NQ);
    float v = -1e30f;
    if (c < NQ) {
        int qi = q / GS, qj = q - qi * GS;
        int ki = c / GS, kj = c - ki * GS;
        int t = (qi - ki + GS - 1) * 27 + (qj - kj + GS - 1);
        v = g_pos[t * NH + h];
    }
    g_bias[idx] = v;
}

// ============================================================
// Kernel: weight prep — transpose to [n][k], single fp16
// ============================================================
__global__ __launch_bounds__(256) void wprep_kernel(
    const float* __restrict__ wq, const float* __restrict__ wkv,
    const float* __restrict__ wproj)
{
    int idx = blockIdx.x * 256 + threadIdx.x;
    if (idx < KVN * CDIM) {
        int n = idx >> 7, k = idx & 127;
        float v = (n < 128) ? wq[k * 128 + n] : wkv[k * 256 + (n - 128)];
        g_wqkv[idx] = __float2half(v);
    } else if (idx < KVN * CDIM + CDIM * CDIM) {
        int j = idx - KVN * CDIM;
        int n = j >> 7, k = j & 127;
        g_wp[j] = __float2half(wproj[k * 128 + n]);
    }
}

// ============================================================
// Kernel: HMMA GEMM
//   SPLIT=true  (qkv): A fp32 -> fp16 hi/lo, 2-term, C fp32
//   SPLIT=false (proj): A fp16 (g_atth), 1-term, C fp32 + bias
//   m64 CTA, m32n16 warp tiles, 64-row B chunks double-buffered
// ============================================================
#define SM_AH 0
#define SM_AL 16384
#define SM_B  32768            // 2 buffers x 16KB
#define GSMEM 65536

template<bool SPLIT>
__global__ __launch_bounds__(256, 3) void hmma_gemm_kernel(
    const float* __restrict__ Ain,
    float* __restrict__ Cout, const float* __restrict__ bias)
{
    extern __shared__ char smc[];
    const uint32_t sb = smem_u32(smc);
    const int tid = threadIdx.x;
    const int w = tid >> 5, lane = tid & 31;
    const int m0 = blockIdx.x * 64;

    float* C = SPLIT ? g_qkv : Cout;
    const __half* B = SPLIT ? g_wqkv : g_wp;
    const int NCH = SPLIT ? 6 : 2;            // 64-row B chunks
    const int ldc = SPLIT ? KVN : CDIM;

    // ---- stage A ----
    if (SPLIT) {
        for (int idx = tid; idx < 1024; idx += 256) {
            int row = idx >> 4, c = idx & 15;
            const float* src = Ain + (size_t)(m0 + row) * CDIM + c * 8;
            float4 v0 = *(const float4*)src;
            float4 v1 = *(const float4*)(src + 4);
            float f[8] = {v0.x, v0.y, v0.z, v0.w, v1.x, v1.y, v1.z, v1.w};
            uint32_t hp[4], lp[4];
#pragma unroll
            for (int q = 0; q < 4; q++)
                split2h(f[2 * q], f[2 * q + 1], hp[q], lp[q]);
            uint32_t off = swz(row, c);
            *(uint4*)(smc + SM_AH + off) = make_uint4(hp[0], hp[1], hp[2], hp[3]);
            *(uint4*)(smc + SM_AL + off) = make_uint4(lp[0], lp[1], lp[2], lp[3]);
        }
    } else {
        for (int idx = tid; idx < 1024; idx += 256) {
            int row = idx >> 4, c = idx & 15;
            uint4 v = *(const uint4*)(g_atth + (size_t)(m0 + row) * CDIM + c * 8);
            *(uint4*)(smc + SM_AH + swz(row, c)) = v;
        }
    }

    // prefetch B chunk 0 (64 rows)
    {
        for (int idx = tid; idx < 1024; idx += 256) {
            int row = idx >> 4, c = idx & 15;
            cpasync16(sb + SM_B + swz(row, c), B + (size_t)row * CDIM + c * 8);
        }
        asm volatile("cp.async.commit_group;");
    }

    const int wm = w >> 2;        // 0..1 -> 32 m-rows
    const int wn = w & 3;         // 0..3 -> 16 n-cols of the 64-col chunk
    const int lrow = lane & 15;
    const int lchunk = lane >> 4;

    for (int ch = 0; ch < NCH; ch++) {
        const int n0 = ch * 64;
        if (ch + 1 < NCH) {
            for (int idx = tid; idx < 1024; idx += 256) {
                int row = idx >> 4, c = idx & 15;
                uint32_t dst = sb + SM_B + ((ch + 1) & 1) * 16384 + swz(row, c);
                cpasync16(dst, B + (size_t)(n0 + 64 + row) * CDIM + c * 8);
            }
            asm volatile("cp.async.commit_group;");
            asm volatile("cp.async.wait_group 1;");
        } else {
            asm volatile("cp.async.wait_group 0;");
        }
        __syncthreads();

        const uint32_t bb = sb + SM_B + (ch & 1) * 16384;

        float d[2][2][4];
#pragma unroll
        for (int mi = 0; mi < 2; mi++)
#pragma unroll
            for (int ni = 0; ni < 2; ni++)
#pragma unroll
                for (int q = 0; q < 4; q++) d[mi][ni][q] = 0.f;

#pragma unroll
        for (int ks = 0; ks < 8; ks++) {
            const int chunk = ks * 2 + lchunk;
            uint32_t ah[2][4], al[2][4];
#pragma unroll
            for (int mi = 0; mi < 2; mi++) {
                int arow = wm * 32 + mi * 16 + lrow;
                ldsm_x4(ah[mi][0], ah[mi][1], ah[mi][2], ah[mi][3],
                        sb + SM_AH + swz(arow, chunk));
                if (SPLIT)
                    ldsm_x4(al[mi][0], al[mi][1], al[mi][2], al[mi][3],
                            sb + SM_AL + swz(arow, chunk));
            }
            int brow = wn * 16 + lrow;
            uint32_t r0, r1, r2, r3;
            ldsm_x4(r0, r1, r2, r3, bb + swz(brow, chunk));
            uint32_t b0[2] = {r0, r2}, b1[2] = {r1, r3};
#pragma unroll
            for (int mi = 0; mi < 2; mi++) {
                mma16816h(d[mi][0], ah[mi], b0);
                mma16816h(d[mi][1], ah[mi], b1);
                if (SPLIT) {
                    mma16816h(d[mi][0], al[mi], b0);
                    mma16816h(d[mi][1], al[mi], b1);
                }
            }
        }
        __syncthreads();   // compute done before next prefetch overwrites buffer

#pragma unroll
        for (int mi = 0; mi < 2; mi++) {
            const int mrow = m0 + wm * 32 + mi * 16 + (lane >> 2);
            const int ncol = n0 + wn * 16 + (lane & 3) * 2;
#pragma unroll
            for (int ni = 0; ni < 2; ni++) {
                float b0 = 0.f, b1 = 0.f;
                if (!SPLIT) {
                    b0 = bias[ncol + ni * 8];
                    b1 = bias[ncol + ni * 8 + 1];
                }
                float* p0 = C + (size_t)mrow * ldc + ncol + ni * 8;
                float* p1 = C + (size_t)(mrow + 8) * ldc + ncol + ni * 8;
                *(float2*)p0 = make_float2(d[mi][ni][0] + b0, d[mi][ni][1] + b1);
                *(float2*)p1 = make_float2(d[mi][ni][2] + b0, d[mi][ni][3] + b1);
            }
        }
    }
}

// ============================================================
// HMMA flash attention (fp16): one CTA per (b,h), 8 warps, 3 CTAs/SM
//   Q hi/lo fp16: [208 rows][32 d], stride 80 B
//   K single fp16 (2-term QKT: QhKh + QlKh)
//   Vt single fp16: [32 d][208 kk], stride 432 B
//   column sweep in 4 passes (8/6/6/6 tiles) to cap S-register pressure
// ============================================================
#define AQH 0
#define AQL 16640
#define AKH 33280
#define AVTH 49920
#define ATTN_SMEM 63744

template<int NSTART, int NT>
__device__ __forceinline__ void half_pass(
    uint32_t qh, uint32_t ql, uint32_t kh, uint32_t vth,
    const float* __restrict__ bias0, const float* __restrict__ bias1,
    int m0, int lane,
    float o[4][4], float& mo0, float& mo1, float& sum0, float& sum1)
{
    const int lrow = lane & 15, lhalf = lane >> 4;
    float S[NT][4];
#pragma unroll
    for (int j = 0; j < NT; j++)
#pragma unroll
        for (int q = 0; q < 4; q++) S[j][q] = 0.f;

    // ---- QK^T: QhKh + QlKh (K single; Kh frag shared by both terms) ----
#pragma unroll
    for (int k0 = 0; k0 < 2; k0++) {
        uint32_t aoff = (uint32_t)((m0 + lrow) * 80 + (k0 * 2 + lhalf) * 16);
        uint32_t a_h[4], a_l[4];
        ldsm_x4(a_h[0], a_h[1], a_h[2], a_h[3], qh + aoff);
        ldsm_x4(a_l[0], a_l[1], a_l[2], a_l[3], ql + aoff);
#pragma unroll
        for (int np = 0; np < NT / 2; np++) {
            uint32_t r0, r1, r2, r3;
            ldsm_x4(r0, r1, r2, r3,
                    kh + (uint32_t)(((NSTART + 2 * np) * 8 + lrow) * 80
                                    + (k0 * 2 + lhalf) * 16));
            uint32_t b0[2] = {r0, r2}, b1[2] = {r1, r3};
            mma16816h(S[2 * np], a_h, b0);
            mma16816h(S[2 * np + 1], a_h, b1);
            mma16816h(S[2 * np], a_l, b0);
            mma16816h(S[2 * np + 1], a_l, b1);
        }
    }

    // ---- bias (mask pre-folded) + row max ----
    float ml0 = -1e30f, ml1 = -1e30f;
#pragma unroll
    for (int j = 0; j < NT; j++) {
        float2 v0 = *(const float2*)(bias0 + NSTART * 8 + j * 8);
        float2 v1 = *(const float2*)(bias1 + NSTART * 8 + j * 8);
        S[j][0] += v0.x; S[j][1] += v0.y;
        S[j][2] += v1.x; S[j][3] += v1.y;
        ml0 = fmaxf(ml0, fmaxf(S[j][0], S[j][1]));
        ml1 = fmaxf(ml1, fmaxf(S[j][2], S[j][3]));
    }
    ml0 = fmaxf(ml0, __shfl_xor_sync(0xffffffffu, ml0, 1));
    ml0 = fmaxf(ml0, __shfl_xor_sync(0xffffffffu, ml0, 2));
    ml1 = fmaxf(ml1, __shfl_xor_sync(0xffffffffu, ml1, 1));
    ml1 = fmaxf(ml1, __shfl_xor_sync(0xffffffffu, ml1, 2));
    float mn0 = fmaxf(mo0, ml0), mn1 = fmaxf(mo1, ml1);
    float f0 = __expf(mo0 - mn0), f1 = __expf(mo1 - mn1);
    mo0 = mn0; mo1 = mn1;
    sum0 *= f0; sum1 *= f1;
#pragma unroll
    for (int n = 0; n < 4; n++) {
        o[n][0] *= f0; o[n][1] *= f0;
        o[n][2] *= f1; o[n][3] *= f1;
    }

    // ---- P = exp(S-m) -> fp16 frags; PV single term ----
#pragma unroll
    for (int t = 0; t < NT / 2; t++) {
        uint32_t ah[4];
#pragma unroll
        for (int jj = 0; jj < 2; jj++) {
            int j = 2 * t + jj;
            float p0 = __expf(S[j][0] - mn0);
            float p1 = __expf(S[j][1] - mn0);
            float p2 = __expf(S[j][2] - mn1);
            float p3 = __expf(S[j][3] - mn1);
            sum0 += p0 + p1; sum1 += p2 + p3;
            ah[2 * jj]     = pack2h(p0, p1);
            ah[2 * jj + 1] = pack2h(p2, p3);
        }
        int kchunk = NSTART + 2 * t + lhalf;
#pragma unroll
        for (int np = 0; np < 2; np++) {
            uint32_t r0, r1, r2, r3;
            ldsm_x4(r0, r1, r2, r3,
                    vth + (uint32_t)((np * 16 + lrow) * 432 + kchunk * 16));
            uint32_t b0[2] = {r0, r2}, b1[2] = {r1, r3};
            mma16816h(o[2 * np], ah, b0);
            mma16816h(o[2 * np + 1], ah, b1);
        }
    }
}

__global__ __launch_bounds__(256, 3) void fattn_kernel()
{
    extern __shared__ char smb[];
    const uint32_t sb = smem_u32(smb);
    const int b = blockIdx.x, h = blockIdx.y;
    const int tid = threadIdx.x;

    // ---- stage q*scale hi/lo, k single, v single (fp16, Vt transposed) ----
    const float* base = g_qkv + (size_t)b * NQ * KVN + h * HD;
    for (int idx = tid; idx < 208 * 32; idx += 256) {
        int n = idx >> 5, d = idx & 31;
        float qv = 0.f, kv = 0.f, vv = 0.f;
        if (n < NQ) {
            const float* row = base + (size_t)n * KVN;
            qv = row[d] * SCALE;
            kv = row[128 + d];
            vv = row[256 + d];
        }
        __half qhh = __float2half(qv);
        __half qll = __float2half(qv - __half2float(qhh));
        *(__half*)(smb + AQH + n * 80 + d * 2) = qhh;
        *(__half*)(smb + AQL + n * 80 + d * 2) = qll;
        *(__half*)(smb + AKH + n * 80 + d * 2) = __float2half(kv);
        *(__half*)(smb + AVTH + d * 432 + n * 2) = __float2half(vv);
    }
    __syncthreads();

    const int w = tid >> 5, lane = tid & 31;
    for (int s = w; s < 13; s += 8) {
        const int m0 = s * 16;
        const int row0 = m0 + (lane >> 2), row1 = row0 + 8;
        const int rc0 = min(row0, NQ - 1), rc1 = min(row1, NQ - 1);
        const float* bias0 = g_bias + ((size_t)h * NQ + rc0) * NCP + (lane & 3) * 2;
        const float* bias1 = g_bias + ((size_t)h * NQ + rc1) * NCP + (lane & 3) * 2;

        float o[4][4];
#pragma unroll
        for (int n = 0; n < 4; n++)
#pragma unroll
            for (int q = 0; q < 4; q++) o[n][q] = 0.f;
        float mo0 = -1e30f, mo1 = -1e30f, sum0 = 0.f, sum1 = 0.f;

        half_pass<0, 8>(sb + AQH, sb + AQL, sb + AKH, sb + AVTH,
                        bias0, bias1, m0, lane, o, mo0, mo1, sum0, sum1);
        half_pass<8, 6>(sb + AQH, sb + AQL, sb + AKH, sb + AVTH,
                        bias0, bias1, m0, lane, o, mo0, mo1, sum0, sum1);
        half_pass<14, 6>(sb + AQH, sb + AQL, sb + AKH, sb + AVTH,
                         bias0, bias1, m0, lane, o, mo0, mo1, sum0, sum1);
        half_pass<20, 6>(sb + AQH, sb + AQL, sb + AKH, sb + AVTH,
                         bias0, bias1, m0, lane, o, mo0, mo1, sum0, sum1);

        sum0 += __shfl_xor_sync(0xffffffffu, sum0, 1);
        sum0 += __shfl_xor_sync(0xffffffffu, sum0, 2);
        sum1 += __shfl_xor_sync(0xffffffffu, sum1, 1);
        sum1 += __shfl_xor_sync(0xffffffffu, sum1, 2);
        float i0 = 1.f / sum0, i1 = 1.f / sum1;

#pragma unroll
        for (int n = 0; n < 4; n++) {
            int d0 = n * 8 + (lane & 3) * 2;
            if (row0 < NQ)
                *(uint32_t*)&g_atth[((size_t)b * NQ + row0) * CDIM + h * HD + d0] =
                    pack2h(o[n][0] * i0, o[n][1] * i0);
            if (row1 < NQ)
                *(uint32_t*)&g_atth[((size_t)b * NQ + row1) * CDIM + h * HD + d0] =
                    pack2h(o[n][2] * i1, o[n][3] * i1);
        }
    }
}

// ============================================================
// launch
// ============================================================
extern "C" void kernel_launch(void* const* d_in, const int* in_sizes, int n_in,
                              void* d_out, int out_size)
{
    const float* x     = (const float*)d_in[0];
    const float* wq    = (const float*)d_in[1];
    const float* wkv   = (const float*)d_in[2];
    const float* wproj = (const float*)d_in[3];
    const float* bproj = (const float*)d_in[4];
    const float* pp_w  = (const float*)d_in[5];
    const float* pp_b  = (const float*)d_in[6];
    const float* ln1_g = (const float*)d_in[7];
    const float* ln1_b = (const float*)d_in[8];
    const float* l1_w  = (const float*)d_in[9];
    const float* l1_b  = (const float*)d_in[10];
    const float* ln2_g = (const float*)d_in[11];
    const float* ln2_b = (const float*)d_in[12];
    const float* l2_w  = (const float*)d_in[13];
    const float* l2_b  = (const float*)d_in[14];
    const float* ln3_g = (const float*)d_in[15];
    const float* ln3_b = (const float*)d_in[16];
    const float* l3_w  = (const float*)d_in[17];
    const float* l3_b  = (const float*)d_in[18];
    float* out = (float*)d_out;

    cudaFuncSetAttribute(hmma_gemm_kernel<true>,
                         cudaFuncAttributeMaxDynamicSharedMemorySize, GSMEM);
    cudaFuncSetAttribute(hmma_gemm_kernel<false>,
                         cudaFuncAttributeMaxDynamicSharedMemorySize, GSMEM);
    cudaFuncSetAttribute(fattn_kernel,
                         cudaFuncAttributeMaxDynamicSharedMemorySize, ATTN_SMEM);

    pos_mlp_kernel<<<3, 256>>>(pp_w, pp_b, ln1_g, ln1_b, l1_w, l1_b,
                               ln2_g, ln2_b, l2_w, l2_b,
                               ln3_g, ln3_b, l3_w, l3_b);

    bias_prep_kernel<<<(NH * NQ * NCP + 255) / 256, 256>>>();

    wprep_kernel<<<256, 256>>>(wq, wkv, wproj);

    // QKV: x @ [wq|wkv] -> g_qkv (fp32)
    hmma_gemm_kernel<true><<<MTOT / 64, 256, GSMEM>>>(x, nullptr, nullptr);

    // flash attention -> g_atth (fp16)
    fattn_kernel<<<dim3(BATCH, NH), 256, ATTN_SMEM>>>();

    // Proj: att(fp16) @ wproj + bproj -> out (fp32)
    hmma_gemm_kernel<false><<<MTOT / 64, 256, GSMEM>>>(nullptr, out, bproj);
}

// round 14
// speedup vs baseline: 1.3929x; 1.1079x over previous
#include <cuda_runtime.h>
#include <cuda_bf16.h>
#include <cuda_fp16.h>
#include <math.h>
#include <stdint.h>

#define GS    14
#define NQ    196            // GS*GS
#define CDIM  128
#define NH    4
#define HD    32
#define BATCH 1024
#define MTOT  (BATCH * NQ)   // 200704
#define KVN   384            // q(128) | k(128) | v(128)
#define TAB   729            // (2*GS-1)^2
#define NCP   208            // padded col count
#define SCALE 0.17677669529663688f   // 32^-0.5

// ---- scratch (static device allocations; no cudaMalloc allowed) ----
__device__ __half g_qkvh[(size_t)MTOT * KVN];  // qkv fp16 (q pre-scaled), ~154 MB
__device__ __half g_atth[(size_t)MTOT * CDIM]; // attention out, fp16 (~51 MB)
__device__ float g_pos[TAB * NH];
__device__ float g_bias[NH * NQ * NCP];       // precomputed rpb, cols padded w/ -1e30
__device__ __half g_wqkv[KVN * CDIM];         // [n=384][k=128] fp16
__device__ __half g_wp[CDIM * CDIM];          // [n=128][k=128] fp16

// ============================================================
// helpers
// ============================================================
__device__ __forceinline__ uint32_t smem_u32(const void* p) {
    uint32_t a;
    asm("{ .reg .u64 t; cvta.to.shared.u64 t, %1; cvt.u32.u64 %0, t; }"
        : "=r"(a) : "l"(p));
    return a;
}
__device__ __forceinline__ void ldsm_x4(uint32_t& r0, uint32_t& r1,
                                        uint32_t& r2, uint32_t& r3, uint32_t addr) {
    asm volatile("ldmatrix.sync.aligned.m8n8.x4.shared.b16 {%0,%1,%2,%3}, [%4];"
                 : "=r"(r0), "=r"(r1), "=r"(r2), "=r"(r3) : "r"(addr));
}
// fp16 mma
__device__ __forceinline__ void mma16816h(float* d, const uint32_t* a, const uint32_t* b) {
    asm volatile("mma.sync.aligned.m16n8k16.row.col.f32.f16.f16.f32 "
                 "{%0,%1,%2,%3}, {%4,%5,%6,%7}, {%8,%9}, {%0,%1,%2,%3};"
                 : "+f"(d[0]), "+f"(d[1]), "+f"(d[2]), "+f"(d[3])
                 : "r"(a[0]), "r"(a[1]), "r"(a[2]), "r"(a[3]),
                   "r"(b[0]), "r"(b[1]));
}
// fp16 hi/lo split of two fp32 values -> packed half2 words
__device__ __forceinline__ void split2h(float v0, float v1, uint32_t& hi, uint32_t& lo) {
    __half h0 = __float2half(v0), h1 = __float2half(v1);
    __half2 H = __halves2half2(h0, h1);
    __half2 L = __halves2half2(__float2half(v0 - __half2float(h0)),
                               __float2half(v1 - __half2float(h1)));
    hi = *(uint32_t*)&H;
    lo = *(uint32_t*)&L;
}
__device__ __forceinline__ uint32_t pack2h(float v0, float v1) {
    __half2 H = __halves2half2(__float2half(v0), __float2half(v1));
    return *(uint32_t*)&H;
}
// swizzled byte offset inside a [rows]x128 16-bit tile (256B rows, 16B chunks)
__device__ __forceinline__ uint32_t swz(int row, int chunk) {
    return (uint32_t)(row * 256 + ((chunk ^ (row & 7)) << 4));
}
__device__ __forceinline__ void cpasync16(uint32_t saddr, const void* g) {
    asm volatile("cp.async.cg.shared.global [%0], [%1], 16;"
                 :: "r"(saddr), "l"(g));
}

// ============================================================
// Kernel 1: dynamic position-bias MLP (729 rows, tiny)
// ============================================================
__device__ __forceinline__ void ln_relu8(float* x, const float* g, const float* b) {
    float mu = 0.f;
#pragma unroll
    for (int d = 0; d < 8; d++) mu += x[d];
    mu *= 0.125f;
    float var = 0.f;
#pragma unroll
    for (int d = 0; d < 8; d++) { float t = x[d] - mu; var += t * t; }
    var *= 0.125f;
    float inv = rsqrtf(var + 1e-5f);
#pragma unroll
    for (int d = 0; d < 8; d++) {
        float t = (x[d] - mu) * inv * g[d] + b[d];
        x[d] = t > 0.f ? t : 0.f;
    }
}

__global__ void pos_mlp_kernel(
    const float* __restrict__ pp_w, const float* __restrict__ pp_b,
    const float* __restrict__ ln1_g, const float* __restrict__ ln1_b,
    const float* __restrict__ l1_w,  const float* __restrict__ l1_b,
    const float* __restrict__ ln2_g, const float* __restrict__ ln2_b,
    const float* __restrict__ l2_w,  const float* __restrict__ l2_b,
    const float* __restrict__ ln3_g, const float* __restrict__ ln3_b,
    const float* __restrict__ l3_w,  const float* __restrict__ l3_b)
{
    int m = blockIdx.x * blockDim.x + threadIdx.x;
    if (m >= TAB) return;
    float bi = (float)(m / 27 - 13);
    float bj = (float)(m % 27 - 13);
    float h[8], t[8];
#pragma unroll
    for (int d = 0; d < 8; d++) h[d] = bi * pp_w[d] + bj * pp_w[8 + d] + pp_b[d];
    ln_relu8(h, ln1_g, ln1_b);
#pragma unroll
    for (int j = 0; j < 8; j++) {
        float a = l1_b[j];
#pragma unroll
        for (int d = 0; d < 8; d++) a += h[d] * l1_w[d * 8 + j];
        t[j] = a;
    }
    ln_relu8(t, ln2_g, ln2_b);
#pragma unroll
    for (int j = 0; j < 8; j++) {
        float a = l2_b[j];
#pragma unroll
        for (int d = 0; d < 8; d++) a += t[d] * l2_w[d * 8 + j];
        h[j] = a;
    }
    ln_relu8(h, ln3_g, ln3_b);
#pragma unroll
    for (int j = 0; j < NH; j++) {
        float a = l3_b[j];
#pragma unroll
        for (int d = 0; d < 8; d++) a += h[d] * l3_w[d * NH + j];
        g_pos[m * NH + j] = a;
    }
}

// ============================================================
// Kernel 1b: expand rpb table -> full bias matrix per head
// ============================================================
__global__ __launch_bounds__(256) void bias_prep_kernel()
{
    int idx = blockIdx.x * 256 + threadIdx.x;
    if (idx >= NH * NQ * NCP) return;
    int c = idx % NCP;
    int q = (idx / NCP) % NQ;
    int h = idx / (NCP * NQ);
    float v = -1e30f;
    if (c < NQ) {
        int qi = q / GS, qj = q - qi * GS;
        int ki = c / GS, kj = c - ki * GS;
        int t = (qi - ki + GS - 1) * 27 + (qj - kj + GS - 1);
        v = g_pos[t * NH + h];
    }
    g_bias[idx] = v;
}

// ============================================================
// Kernel: weight prep — transpose to [n][k], single fp16
// ============================================================
__global__ __launch_bounds__(256) void wprep_kernel(
    const float* __restrict__ wq, const float* __restrict__ wkv,
    const float* __restrict__ wproj)
{
    int idx = blockIdx.x * 256 + threadIdx.x;
    if (idx < KVN * CDIM) {
        int n = idx >> 7, k = idx & 127;
        float v = (n < 128) ? wq[k * 128 + n] : wkv[k * 256 + (n - 128)];
        g_wqkv[idx] = __float2half(v);
    } else if (idx < KVN * CDIM + CDIM * CDIM) {
        int j = idx - KVN * CDIM;
        int n = j >> 7, k = j & 127;
        g_wp[j] = __float2half(wproj[k * 128 + n]);
    }
}

// ============================================================
// Kernel: HMMA GEMM
//   SPLIT=true  (qkv): A fp32 -> fp16 hi/lo, 2-term, C fp16 (q scaled)
//   SPLIT=false (proj): A fp16 (g_atth), 1-term, C fp32 + bias
//   m64 CTA, m32n16 warp tiles, 64-row B chunks double-buffered
// ============================================================
#define SM_AH 0
#define SM_AL 16384
#define SM_B  32768            // 2 buffers x 16KB
#define GSMEM 65536

template<bool SPLIT>
__global__ __launch_bounds__(256, 3) void hmma_gemm_kernel(
    const float* __restrict__ Ain,
    float* __restrict__ Cout, const float* __restrict__ bias)
{
    extern __shared__ char smc[];
    const uint32_t sb = smem_u32(smc);
    const int tid = threadIdx.x;
    const int w = tid >> 5, lane = tid & 31;
    const int m0 = blockIdx.x * 64;

    const __half* B = SPLIT ? g_wqkv : g_wp;
    const int NCH = SPLIT ? 6 : 2;            // 64-row B chunks
    const int ldc = SPLIT ? KVN : CDIM;

    // ---- stage A ----
    if (SPLIT) {
        for (int idx = tid; idx < 1024; idx += 256) {
            int row = idx >> 4, c = idx & 15;
            const float* src = Ain + (size_t)(m0 + row) * CDIM + c * 8;
            float4 v0 = *(const float4*)src;
            float4 v1 = *(const float4*)(src + 4);
            float f[8] = {v0.x, v0.y, v0.z, v0.w, v1.x, v1.y, v1.z, v1.w};
            uint32_t hp[4], lp[4];
#pragma unroll
            for (int q = 0; q < 4; q++)
                split2h(f[2 * q], f[2 * q + 1], hp[q], lp[q]);
            uint32_t off = swz(row, c);
            *(uint4*)(smc + SM_AH + off) = make_uint4(hp[0], hp[1], hp[2], hp[3]);
            *(uint4*)(smc + SM_AL + off) = make_uint4(lp[0], lp[1], lp[2], lp[3]);
        }
    } else {
        for (int idx = tid; idx < 1024; idx += 256) {
            int row = idx >> 4, c = idx & 15;
            uint4 v = *(const uint4*)(g_atth + (size_t)(m0 + row) * CDIM + c * 8);
            *(uint4*)(smc + SM_AH + swz(row, c)) = v;
        }
    }

    // prefetch B chunk 0 (64 rows)
    {
        for (int idx = tid; idx < 1024; idx += 256) {
            int row = idx >> 4, c = idx & 15;
            cpasync16(sb + SM_B + swz(row, c), B + (size_t)row * CDIM + c * 8);
        }
        asm volatile("cp.async.commit_group;");
    }

    const int wm = w >> 2;        // 0..1 -> 32 m-rows
    const int wn = w & 3;         // 0..3 -> 16 n-cols of the 64-col chunk
    const int lrow = lane & 15;
    const int lchunk = lane >> 4;

    for (int ch = 0; ch < NCH; ch++) {
        const int n0 = ch * 64;
        if (ch + 1 < NCH) {
            for (int idx = tid; idx < 1024; idx += 256) {
                int row = idx >> 4, c = idx & 15;
                uint32_t dst = sb + SM_B + ((ch + 1) & 1) * 16384 + swz(row, c);
                cpasync16(dst, B + (size_t)(n0 + 64 + row) * CDIM + c * 8);
            }
            asm volatile("cp.async.commit_group;");
            asm volatile("cp.async.wait_group 1;");
        } else {
            asm volatile("cp.async.wait_group 0;");
        }
        __syncthreads();

        const uint32_t bb = sb + SM_B + (ch & 1) * 16384;

        float d[2][2][4];
#pragma unroll
        for (int mi = 0; mi < 2; mi++)
#pragma unroll
            for (int ni = 0; ni < 2; ni++)
#pragma unroll
                for (int q = 0; q < 4; q++) d[mi][ni][q] = 0.f;

#pragma unroll
        for (int ks = 0; ks < 8; ks++) {
            const int chunk = ks * 2 + lchunk;
            uint32_t ah[2][4], al[2][4];
#pragma unroll
            for (int mi = 0; mi < 2; mi++) {
                int arow = wm * 32 + mi * 16 + lrow;
                ldsm_x4(ah[mi][0], ah[mi][1], ah[mi][2], ah[mi][3],
                        sb + SM_AH + swz(arow, chunk));
                if (SPLIT)
                    ldsm_x4(al[mi][0], al[mi][1], al[mi][2], al[mi][3],
                            sb + SM_AL + swz(arow, chunk));
            }
            int brow = wn * 16 + lrow;
            uint32_t r0, r1, r2, r3;
            ldsm_x4(r0, r1, r2, r3, bb + swz(brow, chunk));
            uint32_t b0[2] = {r0, r2}, b1[2] = {r1, r3};
#pragma unroll
            for (int mi = 0; mi < 2; mi++) {
                mma16816h(d[mi][0], ah[mi], b0);
                mma16816h(d[mi][1], ah[mi], b1);
                if (SPLIT) {
                    mma16816h(d[mi][0], al[mi], b0);
                    mma16816h(d[mi][1], al[mi], b1);
                }
            }
        }
        __syncthreads();   // compute done before next prefetch overwrites buffer

#pragma unroll
        for (int mi = 0; mi < 2; mi++) {
            const int mrow = m0 + wm * 32 + mi * 16 + (lane >> 2);
            const int ncol = n0 + wn * 16 + (lane & 3) * 2;
#pragma unroll
            for (int ni = 0; ni < 2; ni++) {
                if (SPLIT) {
                    // q block (cols 0..127) pre-scaled; fp16 store
                    const float sc = (ncol < 128) ? SCALE : 1.f;
                    size_t p0 = (size_t)mrow * KVN + ncol + ni * 8;
                    size_t p1 = (size_t)(mrow + 8) * KVN + ncol + ni * 8;
                    *(uint32_t*)(g_qkvh + p0) =
                        pack2h(d[mi][ni][0] * sc, d[mi][ni][1] * sc);
                    *(uint32_t*)(g_qkvh + p1) =
                        pack2h(d[mi][ni][2] * sc, d[mi][ni][3] * sc);
                } else {
                    float b0 = bias[ncol + ni * 8];
                    float b1 = bias[ncol + ni * 8 + 1];
                    float* p0 = Cout + (size_t)mrow * CDIM + ncol + ni * 8;
                    float* p1 = Cout + (size_t)(mrow + 8) * CDIM + ncol + ni * 8;
                    *(float2*)p0 = make_float2(d[mi][ni][0] + b0, d[mi][ni][1] + b1);
                    *(float2*)p1 = make_float2(d[mi][ni][2] + b0, d[mi][ni][3] + b1);
                }
            }
        }
    }
}

// ============================================================
// HMMA flash attention (fp16): one CTA per (b,h), 8 warps, 3 CTAs/SM
//   Q single fp16 (pre-scaled, pre-rounded by qkv GEMM): 1-term QKT
//   K single fp16; Vt single fp16
//   column sweep in 4 passes (8/6/6/6 tiles)
// ============================================================
#define AQH 0
#define AKH 16640
#define AVTH 33280
#define ATTN_SMEM 47104

template<int NSTART, int NT>
__device__ __forceinline__ void half_pass(
    uint32_t qh, uint32_t kh, uint32_t vth,
    const float* __restrict__ bias0, const float* __restrict__ bias1,
    int m0, int lane,
    float o[4][4], float& mo0, float& mo1, float& sum0, float& sum1)
{
    const int lrow = lane & 15, lhalf = lane >> 4;
    float S[NT][4];
#pragma unroll
    for (int j = 0; j < NT; j++)
#pragma unroll
        for (int q = 0; q < 4; q++) S[j][q] = 0.f;

    // ---- QK^T: single term (Q already fp16-exact) ----
#pragma unroll
    for (int k0 = 0; k0 < 2; k0++) {
        uint32_t aoff = (uint32_t)((m0 + lrow) * 80 + (k0 * 2 + lhalf) * 16);
        uint32_t a_h[4];
        ldsm_x4(a_h[0], a_h[1], a_h[2], a_h[3], qh + aoff);
#pragma unroll
        for (int np = 0; np < NT / 2; np++) {
            uint32_t r0, r1, r2, r3;
            ldsm_x4(r0, r1, r2, r3,
                    kh + (uint32_t)(((NSTART + 2 * np) * 8 + lrow) * 80
                                    + (k0 * 2 + lhalf) * 16));
            uint32_t b0[2] = {r0, r2}, b1[2] = {r1, r3};
            mma16816h(S[2 * np], a_h, b0);
            mma16816h(S[2 * np + 1], a_h, b1);
        }
    }

    // ---- bias (mask pre-folded) + row max ----
    float ml0 = -1e30f, ml1 = -1e30f;
#pragma unroll
    for (int j = 0; j < NT; j++) {
        float2 v0 = *(const float2*)(bias0 + NSTART * 8 + j * 8);
        float2 v1 = *(const float2*)(bias1 + NSTART * 8 + j * 8);
        S[j][0] += v0.x; S[j][1] += v0.y;
        S[j][2] += v1.x; S[j][3] += v1.y;
        ml0 = fmaxf(ml0, fmaxf(S[j][0], S[j][1]));
        ml1 = fmaxf(ml1, fmaxf(S[j][2], S[j][3]));
    }
    ml0 = fmaxf(ml0, __shfl_xor_sync(0xffffffffu, ml0, 1));
    ml0 = fmaxf(ml0, __shfl_xor_sync(0xffffffffu, ml0, 2));
    ml1 = fmaxf(ml1, __shfl_xor_sync(0xffffffffu, ml1, 1));
    ml1 = fmaxf(ml1, __shfl_xor_sync(0xffffffffu, ml1, 2));
    float mn0 = fmaxf(mo0, ml0), mn1 = fmaxf(mo1, ml1);
    float f0 = __expf(mo0 - mn0), f1 = __expf(mo1 - mn1);
    mo0 = mn0; mo1 = mn1;
    sum0 *= f0; sum1 *= f1;
#pragma unroll
    for (int n = 0; n < 4; n++) {
        o[n][0] *= f0; o[n][1] *= f0;
        o[n][2] *= f1; o[n][3] *= f1;
    }

    // ---- P = exp(S-m) -> fp16 frags; PV single term ----
#pragma unroll
    for (int t = 0; t < NT / 2; t++) {
        uint32_t ah[4];
#pragma unroll
        for (int jj = 0; jj < 2; jj++) {
            int j = 2 * t + jj;
            float p0 = __expf(S[j][0] - mn0);
            float p1 = __expf(S[j][1] - mn0);
            float p2 = __expf(S[j][2] - mn1);
            float p3 = __expf(S[j][3] - mn1);
            sum0 += p0 + p1; sum1 += p2 + p3;
            ah[2 * jj]     = pack2h(p0, p1);
            ah[2 * jj + 1] = pack2h(p2, p3);
        }
        int kchunk = NSTART + 2 * t + lhalf;
#pragma unroll
        for (int np = 0; np < 2; np++) {
            uint32_t r0, r1, r2, r3;
            ldsm_x4(r0, r1, r2, r3,
                    vth + (uint32_t)((np * 16 + lrow) * 432 + kchunk * 16));
            uint32_t b0[2] = {r0, r2}, b1[2] = {r1, r3};
            mma16816h(o[2 * np], ah, b0);
            mma16816h(o[2 * np + 1], ah, b1);
        }
    }
}

__global__ __launch_bounds__(256, 3) void fattn_kernel()
{
    extern __shared__ char smb[];
    const uint32_t sb = smem_u32(smb);
    const int b = blockIdx.x, h = blockIdx.y;
    const int tid = threadIdx.x;

    // ---- stage q/k (16B copies) + v transposed, all fp16 ----
    const __half* base = g_qkvh + (size_t)b * NQ * KVN + h * HD;
    for (int idx = tid; idx < 208 * 4; idx += 256) {
        int n = idx >> 2, g = idx & 3;
        int d0 = g * 8;
        uint4 qv = make_uint4(0, 0, 0, 0), kv = qv, vv = qv;
        if (n < NQ) {
            const __half* row = base + (size_t)n * KVN;
            qv = *(const uint4*)(row + d0);
            kv = *(const uint4*)(row + 128 + d0);
            vv = *(const uint4*)(row + 256 + d0);
        }
        *(uint4*)(smb + AQH + n * 80 + d0 * 2) = qv;
        *(uint4*)(smb + AKH + n * 80 + d0 * 2) = kv;
        // scatter v into Vt [32 d][208 kk]
        const __half* vh = (const __half*)&vv;
#pragma unroll
        for (int j = 0; j < 8; j++)
            *(__half*)(smb + AVTH + (d0 + j) * 432 + n * 2) = vh[j];
    }
    __syncthreads();

    const int w = tid >> 5, lane = tid & 31;
    for (int s = w; s < 13; s += 8) {
        const int m0 = s * 16;
        const int row0 = m0 + (lane >> 2), row1 = row0 + 8;
        const int rc0 = min(row0, NQ - 1), rc1 = min(row1, NQ - 1);
        const float* bias0 = g_bias + ((size_t)h * NQ + rc0) * NCP + (lane & 3) * 2;
        const float* bias1 = g_bias + ((size_t)h * NQ + rc1) * NCP + (lane & 3) * 2;

        float o[4][4];
#pragma unroll
        for (int n = 0; n < 4; n++)
#pragma unroll
            for (int q = 0; q < 4; q++) o[n][q] = 0.f;
        float mo0 = -1e30f, mo1 = -1e30f, sum0 = 0.f, sum1 = 0.f;

        half_pass<0, 8>(sb + AQH, sb + AKH, sb + AVTH,
                        bias0, bias1, m0, lane, o, mo0, mo1, sum0, sum1);
        half_pass<8, 6>(sb + AQH, sb + AKH, sb + AVTH,
                        bias0, bias1, m0, lane, o, mo0, mo1, sum0, sum1);
        half_pass<14, 6>(sb + AQH, sb + AKH, sb + AVTH,
                         bias0, bias1, m0, lane, o, mo0, mo1, sum0, sum1);
        half_pass<20, 6>(sb + AQH, sb + AKH, sb + AVTH,
                         bias0, bias1, m0, lane, o, mo0, mo1, sum0, sum1);

        sum0 += __shfl_xor_sync(0xffffffffu, sum0, 1);
        sum0 += __shfl_xor_sync(0xffffffffu, sum0, 2);
        sum1 += __shfl_xor_sync(0xffffffffu, sum1, 1);
        sum1 += __shfl_xor_sync(0xffffffffu, sum1, 2);
        float i0 = 1.f / sum0, i1 = 1.f / sum1;

#pragma unroll
        for (int n = 0; n < 4; n++) {
            int d0 = n * 8 + (lane & 3) * 2;
            if (row0 < NQ)
                *(uint32_t*)&g_atth[((size_t)b * NQ + row0) * CDIM + h * HD + d0] =
                    pack2h(o[n][0] * i0, o[n][1] * i0);
            if (row1 < NQ)
                *(uint32_t*)&g_atth[((size_t)b * NQ + row1) * CDIM + h * HD + d0] =
                    pack2h(o[n][2] * i1, o[n][3] * i1);
        }
    }
}

// ============================================================
// launch
// ============================================================
extern "C" void kernel_launch(void* const* d_in, const int* in_sizes, int n_in,
                              void* d_out, int out_size)
{
    const float* x     = (const float*)d_in[0];
    const float* wq    = (const float*)d_in[1];
    const float* wkv   = (const float*)d_in[2];
    const float* wproj = (const float*)d_in[3];
    const float* bproj = (const float*)d_in[4];
    const float* pp_w  = (const float*)d_in[5];
    const float* pp_b  = (const float*)d_in[6];
    const float* ln1_g = (const float*)d_in[7];
    const float* ln1_b = (const float*)d_in[8];
    const float* l1_w  = (const float*)d_in[9];
    const float* l1_b  = (const float*)d_in[10];
    const float* ln2_g = (const float*)d_in[11];
    const float* ln2_b = (const float*)d_in[12];
    const float* l2_w  = (const float*)d_in[13];
    const float* l2_b  = (const float*)d_in[14];
    const float* ln3_g = (const float*)d_in[15];
    const float* ln3_b = (const float*)d_in[16];
    const float* l3_w  = (const float*)d_in[17];
    const float* l3_b  = (const float*)d_in[18];
    float* out = (float*)d_out;

    cudaFuncSetAttribute(hmma_gemm_kernel<true>,
                         cudaFuncAttributeMaxDynamicSharedMemorySize, GSMEM);
    cudaFuncSetAttribute(hmma_gemm_kernel<false>,
                         cudaFuncAttributeMaxDynamicSharedMemorySize, GSMEM);
    cudaFuncSetAttribute(fattn_kernel,
                         cudaFuncAttributeMaxDynamicSharedMemorySize, ATTN_SMEM);

    pos_mlp_kernel<<<3, 256>>>(pp_w, pp_b, ln1_g, ln1_b, l1_w, l1_b,
                               ln2_g, ln2_b, l2_w, l2_b,
                               ln3_g, ln3_b, l3_w, l3_b);

    bias_prep_kernel<<<(NH * NQ * NCP + 255) / 256, 256>>>();

    wprep_kernel<<<256, 256>>>(wq, wkv, wproj);

    // QKV: x @ [wq|wkv] -> g_qkvh (fp16, q pre-scaled)
    hmma_gemm_kernel<true><<<MTOT / 64, 256, GSMEM>>>(x, nullptr, nullptr);

    // flash attention -> g_atth (fp16)
    fattn_kernel<<<dim3(BATCH, NH), 256, ATTN_SMEM>>>();

    // Proj: att(fp16) @ wproj + bproj -> out (fp32)
    hmma_gemm_kernel<false><<<MTOT / 64, 256, GSMEM>>>(nullptr, out, bproj);
}

// round 15
// speedup vs baseline: 1.5298x; 1.0983x over previous
#include <cuda_runtime.h>
#include <cuda_bf16.h>
#include <cuda_fp16.h>
#include <math.h>
#include <stdint.h>

#define GS    14
#define NQ    196            // GS*GS
#define CDIM  128
#define NH    4
#define HD    32
#define BATCH 1024
#define MTOT  (BATCH * NQ)   // 200704
#define KVN   384            // q(128) | k(128) | v(128)
#define TAB   729            // (2*GS-1)^2
#define NCP   208            // padded col count
#define SCALE 0.17677669529663688f   // 32^-0.5

// ---- scratch (static device allocations; no cudaMalloc allowed) ----
__device__ __half g_qkvh[(size_t)MTOT * KVN];  // qkv fp16 (q pre-scaled), ~154 MB
__device__ __half g_atth[(size_t)MTOT * CDIM]; // attention out, fp16 (~51 MB)
__device__ float g_pos[TAB * NH];
__device__ float g_bias[NH * NQ * NCP];       // precomputed rpb, cols padded w/ -1e30
__device__ __half g_wqkv[KVN * CDIM];         // [n=384][k=128] fp16
__device__ __half g_wp[CDIM * CDIM];          // [n=128][k=128] fp16

// ============================================================
// helpers
// ============================================================
__device__ __forceinline__ uint32_t smem_u32(const void* p) {
    uint32_t a;
    asm("{ .reg .u64 t; cvta.to.shared.u64 t, %1; cvt.u32.u64 %0, t; }"
        : "=r"(a) : "l"(p));
    return a;
}
__device__ __forceinline__ void ldsm_x4(uint32_t& r0, uint32_t& r1,
                                        uint32_t& r2, uint32_t& r3, uint32_t addr) {
    asm volatile("ldmatrix.sync.aligned.m8n8.x4.shared.b16 {%0,%1,%2,%3}, [%4];"
                 : "=r"(r0), "=r"(r1), "=r"(r2), "=r"(r3) : "r"(addr));
}
// fp16 mma
__device__ __forceinline__ void mma16816h(float* d, const uint32_t* a, const uint32_t* b) {
    asm volatile("mma.sync.aligned.m16n8k16.row.col.f32.f16.f16.f32 "
                 "{%0,%1,%2,%3}, {%4,%5,%6,%7}, {%8,%9}, {%0,%1,%2,%3};"
                 : "+f"(d[0]), "+f"(d[1]), "+f"(d[2]), "+f"(d[3])
                 : "r"(a[0]), "r"(a[1]), "r"(a[2]), "r"(a[3]),
                   "r"(b[0]), "r"(b[1]));
}
__device__ __forceinline__ uint32_t pack2h(float v0, float v1) {
    __half2 H = __halves2half2(__float2half(v0), __float2half(v1));
    return *(uint32_t*)&H;
}
// swizzled byte offset inside a [rows]x128 16-bit tile (256B rows, 16B chunks)
__device__ __forceinline__ uint32_t swz(int row, int chunk) {
    return (uint32_t)(row * 256 + ((chunk ^ (row & 7)) << 4));
}
__device__ __forceinline__ void cpasync16(uint32_t saddr, const void* g) {
    asm volatile("cp.async.cg.shared.global [%0], [%1], 16;"
                 :: "r"(saddr), "l"(g));
}

// ============================================================
// Kernel 1: dynamic position-bias MLP (729 rows, tiny)
// ============================================================
__device__ __forceinline__ void ln_relu8(float* x, const float* g, const float* b) {
    float mu = 0.f;
#pragma unroll
    for (int d = 0; d < 8; d++) mu += x[d];
    mu *= 0.125f;
    float var = 0.f;
#pragma unroll
    for (int d = 0; d < 8; d++) { float t = x[d] - mu; var += t * t; }
    var *= 0.125f;
    float inv = rsqrtf(var + 1e-5f);
#pragma unroll
    for (int d = 0; d < 8; d++) {
        float t = (x[d] - mu) * inv * g[d] + b[d];
        x[d] = t > 0.f ? t : 0.f;
    }
}

__global__ void pos_mlp_kernel(
    const float* __restrict__ pp_w, const float* __restrict__ pp_b,
    const float* __restrict__ ln1_g, const float* __restrict__ ln1_b,
    const float* __restrict__ l1_w,  const float* __restrict__ l1_b,
    const float* __restrict__ ln2_g, const float* __restrict__ ln2_b,
    const float* __restrict__ l2_w,  const float* __restrict__ l2_b,
    const float* __restrict__ ln3_g, const float* __restrict__ ln3_b,
    const float* __restrict__ l3_w,  const float* __restrict__ l3_b)
{
    int m = blockIdx.x * blockDim.x + threadIdx.x;
    if (m >= TAB) return;
    float bi = (float)(m / 27 - 13);
    float bj = (float)(m % 27 - 13);
    float h[8], t[8];
#pragma unroll
    for (int d = 0; d < 8; d++) h[d] = bi * pp_w[d] + bj * pp_w[8 + d] + pp_b[d];
    ln_relu8(h, ln1_g, ln1_b);
#pragma unroll
    for (int j = 0; j < 8; j++) {
        float a = l1_b[j];
#pragma unroll
        for (int d = 0; d < 8; d++) a += h[d] * l1_w[d * 8 + j];
        t[j] = a;
    }
    ln_relu8(t, ln2_g, ln2_b);
#pragma unroll
    for (int j = 0; j < 8; j++) {
        float a = l2_b[j];
#pragma unroll
        for (int d = 0; d < 8; d++) a += t[d] * l2_w[d * 8 + j];
        h[j] = a;
    }
    ln_relu8(h, ln3_g, ln3_b);
#pragma unroll
    for (int j = 0; j < NH; j++) {
        float a = l3_b[j];
#pragma unroll
        for (int d = 0; d < 8; d++) a += h[d] * l3_w[d * NH + j];
        g_pos[m * NH + j] = a;
    }
}

// ============================================================
// Kernel 1b: expand rpb table -> full bias matrix per head
// ============================================================
__global__ __launch_bounds__(256) void bias_prep_kernel()
{
    int idx = blockIdx.x * 256 + threadIdx.x;
    if (idx >= NH * NQ * NCP) return;
    int c = idx % NCP;
    int q = (idx / NCP) % NQ;
    int h = idx / (NCP * NQ);
    float v = -1e30f;
    if (c < NQ) {
        int qi = q / GS, qj = q - qi * GS;
        int ki = c / GS, kj = c - ki * GS;
        int t = (qi - ki + GS - 1) * 27 + (qj - kj + GS - 1);
        v = g_pos[t * NH + h];
    }
    g_bias[idx] = v;
}

// ============================================================
// Kernel: weight prep — transpose to [n][k], single fp16
// ============================================================
__global__ __launch_bounds__(256) void wprep_kernel(
    const float* __restrict__ wq, const float* __restrict__ wkv,
    const float* __restrict__ wproj)
{
    int idx = blockIdx.x * 256 + threadIdx.x;
    if (idx < KVN * CDIM) {
        int n = idx >> 7, k = idx & 127;
        float v = (n < 128) ? wq[k * 128 + n] : wkv[k * 256 + (n - 128)];
        g_wqkv[idx] = __float2half(v);
    } else if (idx < KVN * CDIM + CDIM * CDIM) {
        int j = idx - KVN * CDIM;
        int n = j >> 7, k = j & 127;
        g_wp[j] = __float2half(wproj[k * 128 + n]);
    }
}

// ============================================================
// Kernel: HMMA GEMM, pure 1-term fp16
//   QKV=true:  A = x (fp32 -> fp16 at stage), C = g_qkvh fp16 (q scaled)
//   QKV=false: A = g_atth (fp16), C = fp32 out + bias
//   m64 CTA, m32n16 warp tiles, 64-row B chunks double-buffered
//   smem 48KB -> 3 CTAs/SM
// ============================================================
#define SM_AH 0
#define SM_B  16384            // 2 buffers x 16KB
#define GSMEM 49152

template<bool QKV>
__global__ __launch_bounds__(256, 3) void hmma_gemm_kernel(
    const float* __restrict__ Ain,
    float* __restrict__ Cout, const float* __restrict__ bias)
{
    extern __shared__ char smc[];
    const uint32_t sb = smem_u32(smc);
    const int tid = threadIdx.x;
    const int w = tid >> 5, lane = tid & 31;
    const int m0 = blockIdx.x * 64;

    const __half* B = QKV ? g_wqkv : g_wp;
    const int NCH = QKV ? 6 : 2;              // 64-row B chunks

    // ---- stage A: 64 rows -> single fp16, swizzled smem ----
    if (QKV) {
        for (int idx = tid; idx < 1024; idx += 256) {
            int row = idx >> 4, c = idx & 15;
            const float* src = Ain + (size_t)(m0 + row) * CDIM + c * 8;
            float4 v0 = *(const float4*)src;
            float4 v1 = *(const float4*)(src + 4);
            uint4 o;
            o.x = pack2h(v0.x, v0.y);
            o.y = pack2h(v0.z, v0.w);
            o.z = pack2h(v1.x, v1.y);
            o.w = pack2h(v1.z, v1.w);
            *(uint4*)(smc + SM_AH + swz(row, c)) = o;
        }
    } else {
        for (int idx = tid; idx < 1024; idx += 256) {
            int row = idx >> 4, c = idx & 15;
            uint4 v = *(const uint4*)(g_atth + (size_t)(m0 + row) * CDIM + c * 8);
            *(uint4*)(smc + SM_AH + swz(row, c)) = v;
        }
    }

    // prefetch B chunk 0 (64 rows)
    {
        for (int idx = tid; idx < 1024; idx += 256) {
            int row = idx >> 4, c = idx & 15;
            cpasync16(sb + SM_B + swz(row, c), B + (size_t)row * CDIM + c * 8);
        }
        asm volatile("cp.async.commit_group;");
    }

    const int wm = w >> 2;        // 0..1 -> 32 m-rows
    const int wn = w & 3;         // 0..3 -> 16 n-cols of the 64-col chunk
    const int lrow = lane & 15;
    const int lchunk = lane >> 4;

    for (int ch = 0; ch < NCH; ch++) {
        const int n0 = ch * 64;
        if (ch + 1 < NCH) {
            for (int idx = tid; idx < 1024; idx += 256) {
                int row = idx >> 4, c = idx & 15;
                uint32_t dst = sb + SM_B + ((ch + 1) & 1) * 16384 + swz(row, c);
                cpasync16(dst, B + (size_t)(n0 + 64 + row) * CDIM + c * 8);
            }
            asm volatile("cp.async.commit_group;");
            asm volatile("cp.async.wait_group 1;");
        } else {
            asm volatile("cp.async.wait_group 0;");
        }
        __syncthreads();

        const uint32_t bb = sb + SM_B + (ch & 1) * 16384;

        float d[2][2][4];
#pragma unroll
        for (int mi = 0; mi < 2; mi++)
#pragma unroll
            for (int ni = 0; ni < 2; ni++)
#pragma unroll
                for (int q = 0; q < 4; q++) d[mi][ni][q] = 0.f;

#pragma unroll
        for (int ks = 0; ks < 8; ks++) {
            const int chunk = ks * 2 + lchunk;
            uint32_t ah[2][4];
#pragma unroll
            for (int mi = 0; mi < 2; mi++) {
                int arow = wm * 32 + mi * 16 + lrow;
                ldsm_x4(ah[mi][0], ah[mi][1], ah[mi][2], ah[mi][3],
                        sb + SM_AH + swz(arow, chunk));
            }
            int brow = wn * 16 + lrow;
            uint32_t r0, r1, r2, r3;
            ldsm_x4(r0, r1, r2, r3, bb + swz(brow, chunk));
            uint32_t b0[2] = {r0, r2}, b1[2] = {r1, r3};
#pragma unroll
            for (int mi = 0; mi < 2; mi++) {
                mma16816h(d[mi][0], ah[mi], b0);
                mma16816h(d[mi][1], ah[mi], b1);
            }
        }
        __syncthreads();   // compute done before next prefetch overwrites buffer

#pragma unroll
        for (int mi = 0; mi < 2; mi++) {
            const int mrow = m0 + wm * 32 + mi * 16 + (lane >> 2);
            const int ncol = n0 + wn * 16 + (lane & 3) * 2;
#pragma unroll
            for (int ni = 0; ni < 2; ni++) {
                if (QKV) {
                    // q block (cols 0..127) pre-scaled; fp16 store
                    const float sc = (ncol < 128) ? SCALE : 1.f;
                    size_t p0 = (size_t)mrow * KVN + ncol + ni * 8;
                    size_t p1 = (size_t)(mrow + 8) * KVN + ncol + ni * 8;
                    *(uint32_t*)(g_qkvh + p0) =
                        pack2h(d[mi][ni][0] * sc, d[mi][ni][1] * sc);
                    *(uint32_t*)(g_qkvh + p1) =
                        pack2h(d[mi][ni][2] * sc, d[mi][ni][3] * sc);
                } else {
                    float b0 = bias[ncol + ni * 8];
                    float b1 = bias[ncol + ni * 8 + 1];
                    float* p0 = Cout + (size_t)mrow * CDIM + ncol + ni * 8;
                    float* p1 = Cout + (size_t)(mrow + 8) * CDIM + ncol + ni * 8;
                    *(float2*)p0 = make_float2(d[mi][ni][0] + b0, d[mi][ni][1] + b1);
                    *(float2*)p1 = make_float2(d[mi][ni][2] + b0, d[mi][ni][3] + b1);
                }
            }
        }
    }
}

// ============================================================
// HMMA flash attention (fp16): one CTA per (b,h), 8 warps, 3 CTAs/SM
//   Q/K/V single fp16 (Q pre-scaled by qkv GEMM); 1-term QKT, 1-term PV
//   column sweep in 4 passes (8/6/6/6 tiles)
// ============================================================
#define AQH 0
#define AKH 16640
#define AVTH 33280
#define ATTN_SMEM 47104

template<int NSTART, int NT>
__device__ __forceinline__ void half_pass(
    uint32_t qh, uint32_t kh, uint32_t vth,
    const float* __restrict__ bias0, const float* __restrict__ bias1,
    int m0, int lane,
    float o[4][4], float& mo0, float& mo1, float& sum0, float& sum1)
{
    const int lrow = lane & 15, lhalf = lane >> 4;
    float S[NT][4];
#pragma unroll
    for (int j = 0; j < NT; j++)
#pragma unroll
        for (int q = 0; q < 4; q++) S[j][q] = 0.f;

    // ---- QK^T: single term ----
#pragma unroll
    for (int k0 = 0; k0 < 2; k0++) {
        uint32_t aoff = (uint32_t)((m0 + lrow) * 80 + (k0 * 2 + lhalf) * 16);
        uint32_t a_h[4];
        ldsm_x4(a_h[0], a_h[1], a_h[2], a_h[3], qh + aoff);
#pragma unroll
        for (int np = 0; np < NT / 2; np++) {
            uint32_t r0, r1, r2, r3;
            ldsm_x4(r0, r1, r2, r3,
                    kh + (uint32_t)(((NSTART + 2 * np) * 8 + lrow) * 80
                                    + (k0 * 2 + lhalf) * 16));
            uint32_t b0[2] = {r0, r2}, b1[2] = {r1, r3};
            mma16816h(S[2 * np], a_h, b0);
            mma16816h(S[2 * np + 1], a_h, b1);
        }
    }

    // ---- bias (mask pre-folded) + row max ----
    float ml0 = -1e30f, ml1 = -1e30f;
#pragma unroll
    for (int j = 0; j < NT; j++) {
        float2 v0 = *(const float2*)(bias0 + NSTART * 8 + j * 8);
        float2 v1 = *(const float2*)(bias1 + NSTART * 8 + j * 8);
        S[j][0] += v0.x; S[j][1] += v0.y;
        S[j][2] += v1.x; S[j][3] += v1.y;
        ml0 = fmaxf(ml0, fmaxf(S[j][0], S[j][1]));
        ml1 = fmaxf(ml1, fmaxf(S[j][2], S[j][3]));
    }
    ml0 = fmaxf(ml0, __shfl_xor_sync(0xffffffffu, ml0, 1));
    ml0 = fmaxf(ml0, __shfl_xor_sync(0xffffffffu, ml0, 2));
    ml1 = fmaxf(ml1, __shfl_xor_sync(0xffffffffu, ml1, 1));
    ml1 = fmaxf(ml1, __shfl_xor_sync(0xffffffffu, ml1, 2));
    float mn0 = fmaxf(mo0, ml0), mn1 = fmaxf(mo1, ml1);
    float f0 = __expf(mo0 - mn0), f1 = __expf(mo1 - mn1);
    mo0 = mn0; mo1 = mn1;
    sum0 *= f0; sum1 *= f1;
#pragma unroll
    for (int n = 0; n < 4; n++) {
        o[n][0] *= f0; o[n][1] *= f0;
        o[n][2] *= f1; o[n][3] *= f1;
    }

    // ---- P = exp(S-m) -> fp16 frags; PV single term ----
#pragma unroll
    for (int t = 0; t < NT / 2; t++) {
        uint32_t ah[4];
#pragma unroll
        for (int jj = 0; jj < 2; jj++) {
            int j = 2 * t + jj;
            float p0 = __expf(S[j][0] - mn0);
            float p1 = __expf(S[j][1] - mn0);
            float p2 = __expf(S[j][2] - mn1);
            float p3 = __expf(S[j][3] - mn1);
            sum0 += p0 + p1; sum1 += p2 + p3;
            ah[2 * jj]     = pack2h(p0, p1);
            ah[2 * jj + 1] = pack2h(p2, p3);
        }
        int kchunk = NSTART + 2 * t + lhalf;
#pragma unroll
        for (int np = 0; np < 2; np++) {
            uint32_t r0, r1, r2, r3;
            ldsm_x4(r0, r1, r2, r3,
                    vth + (uint32_t)((np * 16 + lrow) * 432 + kchunk * 16));
            uint32_t b0[2] = {r0, r2}, b1[2] = {r1, r3};
            mma16816h(o[2 * np], ah, b0);
            mma16816h(o[2 * np + 1], ah, b1);
        }
    }
}

__global__ __launch_bounds__(256, 3) void fattn_kernel()
{
    extern __shared__ char smb[];
    const uint32_t sb = smem_u32(smb);
    const int b = blockIdx.x, h = blockIdx.y;
    const int tid = threadIdx.x;

    // ---- stage q/k (16B copies) + v transposed, all fp16 ----
    const __half* base = g_qkvh + (size_t)b * NQ * KVN + h * HD;
    for (int idx = tid; idx < 208 * 4; idx += 256) {
        int n = idx >> 2, g = idx & 3;
        int d0 = g * 8;
        uint4 qv = make_uint4(0, 0, 0, 0), kv = qv, vv = qv;
        if (n < NQ) {
            const __half* row = base + (size_t)n * KVN;
            qv = *(const uint4*)(row + d0);
            kv = *(const uint4*)(row + 128 + d0);
            vv = *(const uint4*)(row + 256 + d0);
        }
        *(uint4*)(smb + AQH + n * 80 + d0 * 2) = qv;
        *(uint4*)(smb + AKH + n * 80 + d0 * 2) = kv;
        // scatter v into Vt [32 d][208 kk]
        const __half* vh = (const __half*)&vv;
#pragma unroll
        for (int j = 0; j < 8; j++)
            *(__half*)(smb + AVTH + (d0 + j) * 432 + n * 2) = vh[j];
    }
    __syncthreads();

    const int w = tid >> 5, lane = tid & 31;
    for (int s = w; s < 13; s += 8) {
        const int m0 = s * 16;
        const int row0 = m0 + (lane >> 2), row1 = row0 + 8;
        const int rc0 = min(row0, NQ - 1), rc1 = min(row1, NQ - 1);
        const float* bias0 = g_bias + ((size_t)h * NQ + rc0) * NCP + (lane & 3) * 2;
        const float* bias1 = g_bias + ((size_t)h * NQ + rc1) * NCP + (lane & 3) * 2;

        float o[4][4];
#pragma unroll
        for (int n = 0; n < 4; n++)
#pragma unroll
            for (int q = 0; q < 4; q++) o[n][q] = 0.f;
        float mo0 = -1e30f, mo1 = -1e30f, sum0 = 0.f, sum1 = 0.f;

        half_pass<0, 8>(sb + AQH, sb + AKH, sb + AVTH,
                        bias0, bias1, m0, lane, o, mo0, mo1, sum0, sum1);
        half_pass<8, 6>(sb + AQH, sb + AKH, sb + AVTH,
                        bias0, bias1, m0, lane, o, mo0, mo1, sum0, sum1);
        half_pass<14, 6>(sb + AQH, sb + AKH, sb + AVTH,
                         bias0, bias1, m0, lane, o, mo0, mo1, sum0, sum1);
        half_pass<20, 6>(sb + AQH, sb + AKH, sb + AVTH,
                         bias0, bias1, m0, lane, o, mo0, mo1, sum0, sum1);

        sum0 += __shfl_xor_sync(0xffffffffu, sum0, 1);
        sum0 += __shfl_xor_sync(0xffffffffu, sum0, 2);
        sum1 += __shfl_xor_sync(0xffffffffu, sum1, 1);
        sum1 += __shfl_xor_sync(0xffffffffu, sum1, 2);
        float i0 = 1.f / sum0, i1 = 1.f / sum1;

#pragma unroll
        for (int n = 0; n < 4; n++) {
            int d0 = n * 8 + (lane & 3) * 2;
            if (row0 < NQ)
                *(uint32_t*)&g_atth[((size_t)b * NQ + row0) * CDIM + h * HD + d0] =
                    pack2h(o[n][0] * i0, o[n][1] * i0);
            if (row1 < NQ)
                *(uint32_t*)&g_atth[((size_t)b * NQ + row1) * CDIM + h * HD + d0] =
                    pack2h(o[n][2] * i1, o[n][3] * i1);
        }
    }
}

// ============================================================
// launch
// ============================================================
extern "C" void kernel_launch(void* const* d_in, const int* in_sizes, int n_in,
                              void* d_out, int out_size)
{
    const float* x     = (const float*)d_in[0];
    const float* wq    = (const float*)d_in[1];
    const float* wkv   = (const float*)d_in[2];
    const float* wproj = (const float*)d_in[3];
    const float* bproj = (const float*)d_in[4];
    const float* pp_w  = (const float*)d_in[5];
    const float* pp_b  = (const float*)d_in[6];
    const float* ln1_g = (const float*)d_in[7];
    const float* ln1_b = (const float*)d_in[8];
    const float* l1_w  = (const float*)d_in[9];
    const float* l1_b  = (const float*)d_in[10];
    const float* ln2_g = (const float*)d_in[11];
    const float* ln2_b = (const float*)d_in[12];
    const float* l2_w  = (const float*)d_in[13];
    const float* l2_b  = (const float*)d_in[14];
    const float* ln3_g = (const float*)d_in[15];
    const float* ln3_b = (const float*)d_in[16];
    const float* l3_w  = (const float*)d_in[17];
    const float* l3_b  = (const float*)d_in[18];
    float* out = (float*)d_out;

    cudaFuncSetAttribute(hmma_gemm_kernel<true>,
                         cudaFuncAttributeMaxDynamicSharedMemorySize, GSMEM);
    cudaFuncSetAttribute(hmma_gemm_kernel<false>,
                         cudaFuncAttributeMaxDynamicSharedMemorySize, GSMEM);
    cudaFuncSetAttribute(fattn_kernel,
                         cudaFuncAttributeMaxDynamicSharedMemorySize, ATTN_SMEM);

    pos_mlp_kernel<<<3, 256>>>(pp_w, pp_b, ln1_g, ln1_b, l1_w, l1_b,
                               ln2_g, ln2_b, l2_w, l2_b,
                               ln3_g, ln3_b, l3_w, l3_b);

    bias_prep_kernel<<<(NH * NQ * NCP + 255) / 256, 256>>>();

    wprep_kernel<<<256, 256>>>(wq, wkv, wproj);

    // QKV: x @ [wq|wkv] -> g_qkvh (fp16, q pre-scaled)
    hmma_gemm_kernel<true><<<MTOT / 64, 256, GSMEM>>>(x, nullptr, nullptr);

    // flash attention -> g_atth (fp16)
    fattn_kernel<<<dim3(BATCH, NH), 256, ATTN_SMEM>>>();

    // Proj: att(fp16) @ wproj + bproj -> out (fp32)
    hmma_gemm_kernel<false><<<MTOT / 64, 256, GSMEM>>>(nullptr, out, bproj);
}

// round 16
// speedup vs baseline: 1.5777x; 1.0313x over previous
#include <cuda_runtime.h>
#include <cuda_bf16.h>
#include <cuda_fp16.h>
#include <math.h>
#include <stdint.h>

#define GS    14
#define NQ    196            // GS*GS
#define CDIM  128
#define NH    4
#define HD    32
#define BATCH 1024
#define MTOT  (BATCH * NQ)   // 200704
#define KVN   384            // q(128) | k(128) | v(128)
#define TAB   729            // (2*GS-1)^2
#define NCP   208            // padded col count
#define SCALE 0.17677669529663688f   // 32^-0.5

// ---- scratch (static device allocations; no cudaMalloc allowed) ----
__device__ __half g_qkvh[(size_t)MTOT * KVN];  // qkv fp16 (q pre-scaled), ~154 MB
__device__ __half g_atth[(size_t)MTOT * CDIM]; // attention out, fp16 (~51 MB)
__device__ float g_pos[TAB * NH];
__device__ float g_bias[NH * NQ * NCP];       // precomputed rpb, cols padded w/ -1e30
__device__ __half g_wqkv[KVN * CDIM];         // [n=384][k=128] fp16
__device__ __half g_wp[CDIM * CDIM];          // [n=128][k=128] fp16

// ============================================================
// helpers
// ============================================================
__device__ __forceinline__ uint32_t smem_u32(const void* p) {
    uint32_t a;
    asm("{ .reg .u64 t; cvta.to.shared.u64 t, %1; cvt.u32.u64 %0, t; }"
        : "=r"(a) : "l"(p));
    return a;
}
__device__ __forceinline__ void ldsm_x4(uint32_t& r0, uint32_t& r1,
                                        uint32_t& r2, uint32_t& r3, uint32_t addr) {
    asm volatile("ldmatrix.sync.aligned.m8n8.x4.shared.b16 {%0,%1,%2,%3}, [%4];"
                 : "=r"(r0), "=r"(r1), "=r"(r2), "=r"(r3) : "r"(addr));
}
__device__ __forceinline__ void ldsm_x4t(uint32_t& r0, uint32_t& r1,
                                         uint32_t& r2, uint32_t& r3, uint32_t addr) {
    asm volatile("ldmatrix.sync.aligned.m8n8.x4.trans.shared.b16 {%0,%1,%2,%3}, [%4];"
                 : "=r"(r0), "=r"(r1), "=r"(r2), "=r"(r3) : "r"(addr));
}
// fp16 mma
__device__ __forceinline__ void mma16816h(float* d, const uint32_t* a, const uint32_t* b) {
    asm volatile("mma.sync.aligned.m16n8k16.row.col.f32.f16.f16.f32 "
                 "{%0,%1,%2,%3}, {%4,%5,%6,%7}, {%8,%9}, {%0,%1,%2,%3};"
                 : "+f"(d[0]), "+f"(d[1]), "+f"(d[2]), "+f"(d[3])
                 : "r"(a[0]), "r"(a[1]), "r"(a[2]), "r"(a[3]),
                   "r"(b[0]), "r"(b[1]));
}
__device__ __forceinline__ uint32_t pack2h(float v0, float v1) {
    __half2 H = __halves2half2(__float2half(v0), __float2half(v1));
    return *(uint32_t*)&H;
}
// swizzled byte offset inside a [rows]x128 16-bit tile (256B rows, 16B chunks)
__device__ __forceinline__ uint32_t swz(int row, int chunk) {
    return (uint32_t)(row * 256 + ((chunk ^ (row & 7)) << 4));
}
__device__ __forceinline__ void cpasync16(uint32_t saddr, const void* g) {
    asm volatile("cp.async.cg.shared.global [%0], [%1], 16;"
                 :: "r"(saddr), "l"(g));
}

// ============================================================
// Kernel 1: dynamic position-bias MLP (729 rows, tiny)
// ============================================================
__device__ __forceinline__ void ln_relu8(float* x, const float* g, const float* b) {
    float mu = 0.f;
#pragma unroll
    for (int d = 0; d < 8; d++) mu += x[d];
    mu *= 0.125f;
    float var = 0.f;
#pragma unroll
    for (int d = 0; d < 8; d++) { float t = x[d] - mu; var += t * t; }
    var *= 0.125f;
    float inv = rsqrtf(var + 1e-5f);
#pragma unroll
    for (int d = 0; d < 8; d++) {
        float t = (x[d] - mu) * inv * g[d] + b[d];
        x[d] = t > 0.f ? t : 0.f;
    }
}

__global__ void pos_mlp_kernel(
    const float* __restrict__ pp_w, const float* __restrict__ pp_b,
    const float* __restrict__ ln1_g, const float* __restrict__ ln1_b,
    const float* __restrict__ l1_w,  const float* __restrict__ l1_b,
    const float* __restrict__ ln2_g, const float* __restrict__ ln2_b,
    const float* __restrict__ l2_w,  const float* __restrict__ l2_b,
    const float* __restrict__ ln3_g, const float* __restrict__ ln3_b,
    const float* __restrict__ l3_w,  const float* __restrict__ l3_b)
{
    int m = blockIdx.x * blockDim.x + threadIdx.x;
    if (m >= TAB) return;
    float bi = (float)(m / 27 - 13);
    float bj = (float)(m % 27 - 13);
    float h[8], t[8];
#pragma unroll
    for (int d = 0; d < 8; d++) h[d] = bi * pp_w[d] + bj * pp_w[8 + d] + pp_b[d];
    ln_relu8(h, ln1_g, ln1_b);
#pragma unroll
    for (int j = 0; j < 8; j++) {
        float a = l1_b[j];
#pragma unroll
        for (int d = 0; d < 8; d++) a += h[d] * l1_w[d * 8 + j];
        t[j] = a;
    }
    ln_relu8(t, ln2_g, ln2_b);
#pragma unroll
    for (int j = 0; j < 8; j++) {
        float a = l2_b[j];
#pragma unroll
        for (int d = 0; d < 8; d++) a += t[d] * l2_w[d * 8 + j];
        h[j] = a;
    }
    ln_relu8(h, ln3_g, ln3_b);
#pragma unroll
    for (int j = 0; j < NH; j++) {
        float a = l3_b[j];
#pragma unroll
        for (int d = 0; d < 8; d++) a += h[d] * l3_w[d * NH + j];
        g_pos[m * NH + j] = a;
    }
}

// ============================================================
// Kernel 1b: expand rpb table -> full bias matrix per head
// ============================================================
__global__ __launch_bounds__(256) void bias_prep_kernel()
{
    int idx = blockIdx.x * 256 + threadIdx.x;
    if (idx >= NH * NQ * NCP) return;
    int c = idx % NCP;
    int q = (idx / NCP) % NQ;
    int h = idx / (NCP * NQ);
    float v = -1e30f;
    if (c < NQ) {
        int qi = q / GS, qj = q - qi * GS;
        int ki = c / GS, kj = c - ki * GS;
        int t = (qi - ki + GS - 1) * 27 + (qj - kj + GS - 1);
        v = g_pos[t * NH + h];
    }
    g_bias[idx] = v;
}

// ============================================================
// Kernel: weight prep — transpose to [n][k], single fp16
// ============================================================
__global__ __launch_bounds__(256) void wprep_kernel(
    const float* __restrict__ wq, const float* __restrict__ wkv,
    const float* __restrict__ wproj)
{
    int idx = blockIdx.x * 256 + threadIdx.x;
    if (idx < KVN * CDIM) {
        int n = idx >> 7, k = idx & 127;
        float v = (n < 128) ? wq[k * 128 + n] : wkv[k * 256 + (n - 128)];
        g_wqkv[idx] = __float2half(v);
    } else if (idx < KVN * CDIM + CDIM * CDIM) {
        int j = idx - KVN * CDIM;
        int n = j >> 7, k = j & 127;
        g_wp[j] = __float2half(wproj[k * 128 + n]);
    }
}

// ============================================================
// Kernel: HMMA GEMM, pure 1-term fp16, m128 CTA, m32n32 warp tiles
//   QKV=true:  A = x (fp32 -> fp16 at stage), C = g_qkvh fp16 (q scaled)
//   QKV=false: A = g_atth (fp16), C = fp32 out + bias
//   64-row B chunks double-buffered; smem 64KB -> 3 CTAs/SM
// ============================================================
#define SM_AH 0
#define SM_B  32768            // 2 buffers x 16KB
#define GSMEM 65536

template<bool QKV>
__global__ __launch_bounds__(256, 3) void hmma_gemm_kernel(
    const float* __restrict__ Ain,
    float* __restrict__ Cout, const float* __restrict__ bias)
{
    extern __shared__ char smc[];
    const uint32_t sb = smem_u32(smc);
    const int tid = threadIdx.x;
    const int w = tid >> 5, lane = tid & 31;
    const int m0 = blockIdx.x * 128;

    const __half* B = QKV ? g_wqkv : g_wp;
    const int NCH = QKV ? 6 : 2;              // 64-row B chunks

    // ---- stage A: 128 rows -> single fp16, swizzled smem ----
    if (QKV) {
        for (int idx = tid; idx < 2048; idx += 256) {
            int row = idx >> 4, c = idx & 15;
            const float* src = Ain + (size_t)(m0 + row) * CDIM + c * 8;
            float4 v0 = *(const float4*)src;
            float4 v1 = *(const float4*)(src + 4);
            uint4 o;
            o.x = pack2h(v0.x, v0.y);
            o.y = pack2h(v0.z, v0.w);
            o.z = pack2h(v1.x, v1.y);
            o.w = pack2h(v1.z, v1.w);
            *(uint4*)(smc + SM_AH + swz(row, c)) = o;
        }
    } else {
        for (int idx = tid; idx < 2048; idx += 256) {
            int row = idx >> 4, c = idx & 15;
            uint4 v = *(const uint4*)(g_atth + (size_t)(m0 + row) * CDIM + c * 8);
            *(uint4*)(smc + SM_AH + swz(row, c)) = v;
        }
    }

    // prefetch B chunk 0 (64 rows)
    {
        for (int idx = tid; idx < 1024; idx += 256) {
            int row = idx >> 4, c = idx & 15;
            cpasync16(sb + SM_B + swz(row, c), B + (size_t)row * CDIM + c * 8);
        }
        asm volatile("cp.async.commit_group;");
    }

    const int wm = w >> 1;        // 0..3 -> 32 m-rows
    const int wn = w & 1;         // 0..1 -> 32 n-cols of the 64-col chunk
    const int lrow = lane & 15;
    const int lchunk = lane >> 4;

    for (int ch = 0; ch < NCH; ch++) {
        const int n0 = ch * 64;
        if (ch + 1 < NCH) {
            for (int idx = tid; idx < 1024; idx += 256) {
                int row = idx >> 4, c = idx & 15;
                uint32_t dst = sb + SM_B + ((ch + 1) & 1) * 16384 + swz(row, c);
                cpasync16(dst, B + (size_t)(n0 + 64 + row) * CDIM + c * 8);
            }
            asm volatile("cp.async.commit_group;");
            asm volatile("cp.async.wait_group 1;");
        } else {
            asm volatile("cp.async.wait_group 0;");
        }
        __syncthreads();

        const uint32_t bb = sb + SM_B + (ch & 1) * 16384;

        float d[2][4][4];
#pragma unroll
        for (int mi = 0; mi < 2; mi++)
#pragma unroll
            for (int ni = 0; ni < 4; ni++)
#pragma unroll
                for (int q = 0; q < 4; q++) d[mi][ni][q] = 0.f;

#pragma unroll
        for (int ks = 0; ks < 8; ks++) {
            const int chunk = ks * 2 + lchunk;
            uint32_t a_h[2][4];
#pragma unroll
            for (int mi = 0; mi < 2; mi++) {
                int arow = wm * 32 + mi * 16 + lrow;
                ldsm_x4(a_h[mi][0], a_h[mi][1], a_h[mi][2], a_h[mi][3],
                        sb + SM_AH + swz(arow, chunk));
            }
#pragma unroll
            for (int nj = 0; nj < 2; nj++) {
                int brow = wn * 32 + nj * 16 + lrow;
                uint32_t r0, r1, r2, r3;
                ldsm_x4(r0, r1, r2, r3, bb + swz(brow, chunk));
                uint32_t b0[2] = {r0, r2}, b1[2] = {r1, r3};
#pragma unroll
                for (int mi = 0; mi < 2; mi++) {
                    mma16816h(d[mi][2 * nj], a_h[mi], b0);
                    mma16816h(d[mi][2 * nj + 1], a_h[mi], b1);
                }
            }
        }
        __syncthreads();   // compute done before next prefetch overwrites buffer

#pragma unroll
        for (int mi = 0; mi < 2; mi++) {
            const int mrow = m0 + wm * 32 + mi * 16 + (lane >> 2);
#pragma unroll
            for (int ni = 0; ni < 4; ni++) {
                const int ncol = n0 + wn * 32 + ni * 8 + (lane & 3) * 2;
                if (QKV) {
                    // q block (cols 0..127) pre-scaled; fp16 store
                    const float sc = (ncol < 128) ? SCALE : 1.f;
                    size_t p0 = (size_t)mrow * KVN + ncol;
                    size_t p1 = (size_t)(mrow + 8) * KVN + ncol;
                    *(uint32_t*)(g_qkvh + p0) =
                        pack2h(d[mi][ni][0] * sc, d[mi][ni][1] * sc);
                    *(uint32_t*)(g_qkvh + p1) =
                        pack2h(d[mi][ni][2] * sc, d[mi][ni][3] * sc);
                } else {
                    float b0 = bias[ncol];
                    float b1 = bias[ncol + 1];
                    float* p0 = Cout + (size_t)mrow * CDIM + ncol;
                    float* p1 = Cout + (size_t)(mrow + 8) * CDIM + ncol;
                    *(float2*)p0 = make_float2(d[mi][ni][0] + b0, d[mi][ni][1] + b1);
                    *(float2*)p1 = make_float2(d[mi][ni][2] + b0, d[mi][ni][3] + b1);
                }
            }
        }
    }
}

// ============================================================
// HMMA flash attention (fp16): one CTA per (b,h), 8 warps, 3 CTAs/SM
//   Q/K/V single fp16 rows [208][32 d], stride 80 B (Q pre-scaled)
//   PV B-frags via ldmatrix.trans on V rows (R6-proven pattern)
//   column sweep in 4 passes (8/6/6/6 tiles)
// ============================================================
#define AQH 0
#define AKH 16640
#define AVH 33280
#define ATTN_SMEM 49920

template<int NSTART, int NT>
__device__ __forceinline__ void half_pass(
    uint32_t qh, uint32_t kh, uint32_t vh,
    const float* __restrict__ bias0, const float* __restrict__ bias1,
    int m0, int lane,
    float o[4][4], float& mo0, float& mo1, float& sum0, float& sum1)
{
    const int lrow = lane & 15, lhalf = lane >> 4;
    float S[NT][4];
#pragma unroll
    for (int j = 0; j < NT; j++)
#pragma unroll
        for (int q = 0; q < 4; q++) S[j][q] = 0.f;

    // ---- QK^T: single term ----
#pragma unroll
    for (int k0 = 0; k0 < 2; k0++) {
        uint32_t aoff = (uint32_t)((m0 + lrow) * 80 + (k0 * 2 + lhalf) * 16);
        uint32_t a_h[4];
        ldsm_x4(a_h[0], a_h[1], a_h[2], a_h[3], qh + aoff);
#pragma unroll
        for (int np = 0; np < NT / 2; np++) {
            uint32_t r0, r1, r2, r3;
            ldsm_x4(r0, r1, r2, r3,
                    kh + (uint32_t)(((NSTART + 2 * np) * 8 + lrow) * 80
                                    + (k0 * 2 + lhalf) * 16));
            uint32_t b0[2] = {r0, r2}, b1[2] = {r1, r3};
            mma16816h(S[2 * np], a_h, b0);
            mma16816h(S[2 * np + 1], a_h, b1);
        }
    }

    // ---- bias (mask pre-folded) + row max ----
    float ml0 = -1e30f, ml1 = -1e30f;
#pragma unroll
    for (int j = 0; j < NT; j++) {
        float2 v0 = *(const float2*)(bias0 + NSTART * 8 + j * 8);
        float2 v1 = *(const float2*)(bias1 + NSTART * 8 + j * 8);
        S[j][0] += v0.x; S[j][1] += v0.y;
        S[j][2] += v1.x; S[j][3] += v1.y;
        ml0 = fmaxf(ml0, fmaxf(S[j][0], S[j][1]));
        ml1 = fmaxf(ml1, fmaxf(S[j][2], S[j][3]));
    }
    ml0 = fmaxf(ml0, __shfl_xor_sync(0xffffffffu, ml0, 1));
    ml0 = fmaxf(ml0, __shfl_xor_sync(0xffffffffu, ml0, 2));
    ml1 = fmaxf(ml1, __shfl_xor_sync(0xffffffffu, ml1, 1));
    ml1 = fmaxf(ml1, __shfl_xor_sync(0xffffffffu, ml1, 2));
    float mn0 = fmaxf(mo0, ml0), mn1 = fmaxf(mo1, ml1);
    float f0 = __expf(mo0 - mn0), f1 = __expf(mo1 - mn1);
    mo0 = mn0; mo1 = mn1;
    sum0 *= f0; sum1 *= f1;
#pragma unroll
    for (int n = 0; n < 4; n++) {
        o[n][0] *= f0; o[n][1] *= f0;
        o[n][2] *= f1; o[n][3] *= f1;
    }

    // ---- P = exp(S-m) -> fp16 frags; PV via trans-ldmatrix V ----
#pragma unroll
    for (int t = 0; t < NT / 2; t++) {
        uint32_t ah[4];
#pragma unroll
        for (int jj = 0; jj < 2; jj++) {
            int j = 2 * t + jj;
            float p0 = __expf(S[j][0] - mn0);
            float p1 = __expf(S[j][1] - mn0);
            float p2 = __expf(S[j][2] - mn1);
            float p3 = __expf(S[j][3] - mn1);
            sum0 += p0 + p1; sum1 += p2 + p3;
            ah[2 * jj]     = pack2h(p0, p1);
            ah[2 * jj + 1] = pack2h(p2, p3);
        }
        const int kk0 = NSTART * 8 + t * 16;
#pragma unroll
        for (int dh = 0; dh < 2; dh++) {       // d halves: 0..15, 16..31
            uint32_t r0, r1, r2, r3;
            ldsm_x4t(r0, r1, r2, r3,
                     vh + (uint32_t)((kk0 + lrow) * 80
                                     + (dh * 16 + lhalf * 8) * 2));
            uint32_t b0[2] = {r0, r1}, b1[2] = {r2, r3};
            mma16816h(o[2 * dh], ah, b0);
            mma16816h(o[2 * dh + 1], ah, b1);
        }
    }
}

__global__ __launch_bounds__(256, 3) void fattn_kernel()
{
    extern __shared__ char smb[];
    const uint32_t sb = smem_u32(smb);
    const int b = blockIdx.x, h = blockIdx.y;
    const int tid = threadIdx.x;

    // ---- stage q/k/v rows (pure 16B copies), all fp16 ----
    const __half* base = g_qkvh + (size_t)b * NQ * KVN + h * HD;
    for (int idx = tid; idx < 208 * 4; idx += 256) {
        int n = idx >> 2, g = idx & 3;
        int d0 = g * 8;
        uint4 qv = make_uint4(0, 0, 0, 0), kv = qv, vv = qv;
        if (n < NQ) {
            const __half* row = base + (size_t)n * KVN;
            qv = *(const uint4*)(row + d0);
            kv = *(const uint4*)(row + 128 + d0);
            vv = *(const uint4*)(row + 256 + d0);
        }
        *(uint4*)(smb + AQH + n * 80 + d0 * 2) = qv;
        *(uint4*)(smb + AKH + n * 80 + d0 * 2) = kv;
        *(uint4*)(smb + AVH + n * 80 + d0 * 2) = vv;
    }
    __syncthreads();

    const int w = tid >> 5, lane = tid & 31;
    for (int s = w; s < 13; s += 8) {
        const int m0 = s * 16;
        const int row0 = m0 + (lane >> 2), row1 = row0 + 8;
        const int rc0 = min(row0, NQ - 1), rc1 = min(row1, NQ - 1);
        const float* bias0 = g_bias + ((size_t)h * NQ + rc0) * NCP + (lane & 3) * 2;
        const float* bias1 = g_bias + ((size_t)h * NQ + rc1) * NCP + (lane & 3) * 2;

        float o[4][4];
#pragma unroll
        for (int n = 0; n < 4; n++)
#pragma unroll
            for (int q = 0; q < 4; q++) o[n][q] = 0.f;
        float mo0 = -1e30f, mo1 = -1e30f, sum0 = 0.f, sum1 = 0.f;

        half_pass<0, 8>(sb + AQH, sb + AKH, sb + AVH,
                        bias0, bias1, m0, lane, o, mo0, mo1, sum0, sum1);
        half_pass<8, 6>(sb + AQH, sb + AKH, sb + AVH,
                        bias0, bias1, m0, lane, o, mo0, mo1, sum0, sum1);
        half_pass<14, 6>(sb + AQH, sb + AKH, sb + AVH,
                         bias0, bias1, m0, lane, o, mo0, mo1, sum0, sum1);
        half_pass<20, 6>(sb + AQH, sb + AKH, sb + AVH,
                         bias0, bias1, m0, lane, o, mo0, mo1, sum0, sum1);

        sum0 += __shfl_xor_sync(0xffffffffu, sum0, 1);
        sum0 += __shfl_xor_sync(0xffffffffu, sum0, 2);
        sum1 += __shfl_xor_sync(0xffffffffu, sum1, 1);
        sum1 += __shfl_xor_sync(0xffffffffu, sum1, 2);
        float i0 = 1.f / sum0, i1 = 1.f / sum1;

#pragma unroll
        for (int n = 0; n < 4; n++) {
            int d0 = n * 8 + (lane & 3) * 2;
            if (row0 < NQ)
                *(uint32_t*)&g_atth[((size_t)b * NQ + row0) * CDIM + h * HD + d0] =
                    pack2h(o[n][0] * i0, o[n][1] * i0);
            if (row1 < NQ)
                *(uint32_t*)&g_atth[((size_t)b * NQ + row1) * CDIM + h * HD + d0] =
                    pack2h(o[n][2] * i1, o[n][3] * i1);
        }
    }
}

// ============================================================
// launch
// ============================================================
extern "C" void kernel_launch(void* const* d_in, const int* in_sizes, int n_in,
                              void* d_out, int out_size)
{
    const float* x     = (const float*)d_in[0];
    const float* wq    = (const float*)d_in[1];
    const float* wkv   = (const float*)d_in[2];
    const float* wproj = (const float*)d_in[3];
    const float* bproj = (const float*)d_in[4];
    const float* pp_w  = (const float*)d_in[5];
    const float* pp_b  = (const float*)d_in[6];
    const float* ln1_g = (const float*)d_in[7];
    const float* ln1_b = (const float*)d_in[8];
    const float* l1_w  = (const float*)d_in[9];
    const float* l1_b  = (const float*)d_in[10];
    const float* ln2_g = (const float*)d_in[11];
    const float* ln2_b = (const float*)d_in[12];
    const float* l2_w  = (const float*)d_in[13];
    const float* l2_b  = (const float*)d_in[14];
    const float* ln3_g = (const float*)d_in[15];
    const float* ln3_b = (const float*)d_in[16];
    const float* l3_w  = (const float*)d_in[17];
    const float* l3_b  = (const float*)d_in[18];
    float* out = (float*)d_out;

    cudaFuncSetAttribute(hmma_gemm_kernel<true>,
                         cudaFuncAttributeMaxDynamicSharedMemorySize, GSMEM);
    cudaFuncSetAttribute(hmma_gemm_kernel<false>,
                         cudaFuncAttributeMaxDynamicSharedMemorySize, GSMEM);
    cudaFuncSetAttribute(fattn_kernel,
                         cudaFuncAttributeMaxDynamicSharedMemorySize, ATTN_SMEM);

    pos_mlp_kernel<<<3, 256>>>(pp_w, pp_b, ln1_g, ln1_b, l1_w, l1_b,
                               ln2_g, ln2_b, l2_w, l2_b,
                               ln3_g, ln3_b, l3_w, l3_b);

    bias_prep_kernel<<<(NH * NQ * NCP + 255) / 256, 256>>>();

    wprep_kernel<<<256, 256>>>(wq, wkv, wproj);

    // QKV: x @ [wq|wkv] -> g_qkvh (fp16, q pre-scaled)
    hmma_gemm_kernel<true><<<MTOT / 128, 256, GSMEM>>>(x, nullptr, nullptr);

    // flash attention -> g_atth (fp16)
    fattn_kernel<<<dim3(BATCH, NH), 256, ATTN_SMEM>>>();

    // Proj: att(fp16) @ wproj + bproj -> out (fp32)
    hmma_gemm_kernel<false><<<MTOT / 128, 256, GSMEM>>>(nullptr, out, bproj);
}

// round 17
// speedup vs baseline: 1.6740x; 1.0610x over previous
#include <cuda_runtime.h>
#include <cuda_bf16.h>
#include <cuda_fp16.h>
#include <math.h>
#include <stdint.h>

#define GS    14
#define NQ    196            // GS*GS
#define CDIM  128
#define NH    4
#define HD    32
#define BATCH 1024
#define MTOT  (BATCH * NQ)   // 200704
#define KVN   384            // q(128) | k(128) | v(128)
#define TAB   729            // (2*GS-1)^2
#define NCP   208            // padded col count
#define SCALE 0.17677669529663688f    // 32^-0.5
#define LOG2E 1.4426950408889634f

// ---- scratch (static device allocations; no cudaMalloc allowed) ----
__device__ __half g_qkvh[(size_t)MTOT * KVN];  // qkv fp16 (q pre-scaled by SCALE*LOG2E)
__device__ __half g_atth[(size_t)MTOT * CDIM]; // attention out, fp16
__device__ float g_pos[TAB * NH];
__device__ float g_bias[NH * NQ * NCP];        // rpb * LOG2E, cols padded w/ -1e30
__device__ __half g_wqkv[KVN * CDIM];          // [n=384][k=128] fp16
__device__ __half g_wp[CDIM * CDIM];           // [n=128][k=128] fp16

// ============================================================
// helpers
// ============================================================
__device__ __forceinline__ uint32_t smem_u32(const void* p) {
    uint32_t a;
    asm("{ .reg .u64 t; cvta.to.shared.u64 t, %1; cvt.u32.u64 %0, t; }"
        : "=r"(a) : "l"(p));
    return a;
}
__device__ __forceinline__ void ldsm_x4(uint32_t& r0, uint32_t& r1,
                                        uint32_t& r2, uint32_t& r3, uint32_t addr) {
    asm volatile("ldmatrix.sync.aligned.m8n8.x4.shared.b16 {%0,%1,%2,%3}, [%4];"
                 : "=r"(r0), "=r"(r1), "=r"(r2), "=r"(r3) : "r"(addr));
}
__device__ __forceinline__ void ldsm_x4t(uint32_t& r0, uint32_t& r1,
                                         uint32_t& r2, uint32_t& r3, uint32_t addr) {
    asm volatile("ldmatrix.sync.aligned.m8n8.x4.trans.shared.b16 {%0,%1,%2,%3}, [%4];"
                 : "=r"(r0), "=r"(r1), "=r"(r2), "=r"(r3) : "r"(addr));
}
// fp16 mma
__device__ __forceinline__ void mma16816h(float* d, const uint32_t* a, const uint32_t* b) {
    asm volatile("mma.sync.aligned.m16n8k16.row.col.f32.f16.f16.f32 "
                 "{%0,%1,%2,%3}, {%4,%5,%6,%7}, {%8,%9}, {%0,%1,%2,%3};"
                 : "+f"(d[0]), "+f"(d[1]), "+f"(d[2]), "+f"(d[3])
                 : "r"(a[0]), "r"(a[1]), "r"(a[2]), "r"(a[3]),
                   "r"(b[0]), "r"(b[1]));
}
// single-op fp32x2 -> half2 pack
__device__ __forceinline__ uint32_t pack2h(float v0, float v1) {
    __half2 H = __floats2half2_rn(v0, v1);
    return *(uint32_t*)&H;
}
// single-op exp2
__device__ __forceinline__ float ex2(float x) {
    float y;
    asm("ex2.approx.f32 %0, %1;" : "=f"(y) : "f"(x));
    return y;
}
// swizzled byte offset inside a [rows]x128 16-bit tile (256B rows, 16B chunks)
__device__ __forceinline__ uint32_t swz(int row, int chunk) {
    return (uint32_t)(row * 256 + ((chunk ^ (row & 7)) << 4));
}
__device__ __forceinline__ void cpasync16(uint32_t saddr, const void* g) {
    asm volatile("cp.async.cg.shared.global [%0], [%1], 16;"
                 :: "r"(saddr), "l"(g));
}

// ============================================================
// Kernel 1: dynamic position-bias MLP (729 rows, tiny)
// ============================================================
__device__ __forceinline__ void ln_relu8(float* x, const float* g, const float* b) {
    float mu = 0.f;
#pragma unroll
    for (int d = 0; d < 8; d++) mu += x[d];
    mu *= 0.125f;
    float var = 0.f;
#pragma unroll
    for (int d = 0; d < 8; d++) { float t = x[d] - mu; var += t * t; }
    var *= 0.125f;
    float inv = rsqrtf(var + 1e-5f);
#pragma unroll
    for (int d = 0; d < 8; d++) {
        float t = (x[d] - mu) * inv * g[d] + b[d];
        x[d] = t > 0.f ? t : 0.f;
    }
}

__global__ void pos_mlp_kernel(
    const float* __restrict__ pp_w, const float* __restrict__ pp_b,
    const float* __restrict__ ln1_g, const float* __restrict__ ln1_b,
    const float* __restrict__ l1_w,  const float* __restrict__ l1_b,
    const float* __restrict__ ln2_g, const float* __restrict__ ln2_b,
    const float* __restrict__ l2_w,  const float* __restrict__ l2_b,
    const float* __restrict__ ln3_g, const float* __restrict__ ln3_b,
    const float* __restrict__ l3_w,  const float* __restrict__ l3_b)
{
    int m = blockIdx.x * blockDim.x + threadIdx.x;
    if (m >= TAB) return;
    float bi = (float)(m / 27 - 13);
    float bj = (float)(m % 27 - 13);
    float h[8], t[8];
#pragma unroll
    for (int d = 0; d < 8; d++) h[d] = bi * pp_w[d] + bj * pp_w[8 + d] + pp_b[d];
    ln_relu8(h, ln1_g, ln1_b);
#pragma unroll
    for (int j = 0; j < 8; j++) {
        float a = l1_b[j];
#pragma unroll
        for (int d = 0; d < 8; d++) a += h[d] * l1_w[d * 8 + j];
        t[j] = a;
    }
    ln_relu8(t, ln2_g, ln2_b);
#pragma unroll
    for (int j = 0; j < 8; j++) {
        float a = l2_b[j];
#pragma unroll
        for (int d = 0; d < 8; d++) a += t[d] * l2_w[d * 8 + j];
        h[j] = a;
    }
    ln_relu8(h, ln3_g, ln3_b);
#pragma unroll
    for (int j = 0; j < NH; j++) {
        float a = l3_b[j];
#pragma unroll
        for (int d = 0; d < 8; d++) a += h[d] * l3_w[d * NH + j];
        g_pos[m * NH + j] = a;
    }
}

// ============================================================
// Kernel 1b: expand rpb table -> full bias matrix per head
//   stored in log2 domain (x LOG2E); mask -1e30
// ============================================================
__global__ __launch_bounds__(256) void bias_prep_kernel()
{
    int idx = blockIdx.x * 256 + threadIdx.x;
    if (idx >= NH * NQ * NCP) return;
    int c = idx % NCP;
    int q = (idx / NCP) % NQ;
    int h = idx / (NCP * NQ);
    float v = -1e30f;
    if (c < NQ) {
        int qi = q / GS, qj = q - qi * GS;
        int ki = c / GS, kj = c - ki * GS;
        int t = (qi - ki + GS - 1) * 27 + (qj - kj + GS - 1);
        v = g_pos[t * NH + h] * LOG2E;
    }
    g_bias[idx] = v;
}

// ============================================================
// Kernel: weight prep — transpose to [n][k], single fp16
// ============================================================
__global__ __launch_bounds__(256) void wprep_kernel(
    const float* __restrict__ wq, const float* __restrict__ wkv,
    const float* __restrict__ wproj)
{
    int idx = blockIdx.x * 256 + threadIdx.x;
    if (idx < KVN * CDIM) {
        int n = idx >> 7, k = idx & 127;
        float v = (n < 128) ? wq[k * 128 + n] : wkv[k * 256 + (n - 128)];
        g_wqkv[idx] = __float2half(v);
    } else if (idx < KVN * CDIM + CDIM * CDIM) {
        int j = idx - KVN * CDIM;
        int n = j >> 7, k = j & 127;
        g_wp[j] = __float2half(wproj[k * 128 + n]);
    }
}

// ============================================================
// Kernel: HMMA GEMM, pure 1-term fp16, m128 CTA, m32n32 warp tiles
//   QKV=true:  A = x (fp32 -> fp16 at stage), C = g_qkvh fp16
//              (q block scaled by SCALE*LOG2E for log2-domain softmax)
//   QKV=false: A = g_atth (fp16), C = fp32 out + bias
//   64-row B chunks double-buffered; smem 64KB -> 3 CTAs/SM
// ============================================================
#define SM_AH 0
#define SM_B  32768            // 2 buffers x 16KB
#define GSMEM 65536

template<bool QKV>
__global__ __launch_bounds__(256, 3) void hmma_gemm_kernel(
    const float* __restrict__ Ain,
    float* __restrict__ Cout, const float* __restrict__ bias)
{
    extern __shared__ char smc[];
    const uint32_t sb = smem_u32(smc);
    const int tid = threadIdx.x;
    const int w = tid >> 5, lane = tid & 31;
    const int m0 = blockIdx.x * 128;

    const __half* B = QKV ? g_wqkv : g_wp;
    const int NCH = QKV ? 6 : 2;              // 64-row B chunks

    // ---- stage A: 128 rows -> single fp16, swizzled smem ----
    if (QKV) {
        for (int idx = tid; idx < 2048; idx += 256) {
            int row = idx >> 4, c = idx & 15;
            const float* src = Ain + (size_t)(m0 + row) * CDIM + c * 8;
            float4 v0 = *(const float4*)src;
            float4 v1 = *(const float4*)(src + 4);
            uint4 o;
            o.x = pack2h(v0.x, v0.y);
            o.y = pack2h(v0.z, v0.w);
            o.z = pack2h(v1.x, v1.y);
            o.w = pack2h(v1.z, v1.w);
            *(uint4*)(smc + SM_AH + swz(row, c)) = o;
        }
    } else {
        for (int idx = tid; idx < 2048; idx += 256) {
            int row = idx >> 4, c = idx & 15;
            uint4 v = *(const uint4*)(g_atth + (size_t)(m0 + row) * CDIM + c * 8);
            *(uint4*)(smc + SM_AH + swz(row, c)) = v;
        }
    }

    // prefetch B chunk 0 (64 rows)
    {
        for (int idx = tid; idx < 1024; idx += 256) {
            int row = idx >> 4, c = idx & 15;
            cpasync16(sb + SM_B + swz(row, c), B + (size_t)row * CDIM + c * 8);
        }
        asm volatile("cp.async.commit_group;");
    }

    const int wm = w >> 1;        // 0..3 -> 32 m-rows
    const int wn = w & 1;         // 0..1 -> 32 n-cols of the 64-col chunk
    const int lrow = lane & 15;
    const int lchunk = lane >> 4;

    for (int ch = 0; ch < NCH; ch++) {
        const int n0 = ch * 64;
        if (ch + 1 < NCH) {
            for (int idx = tid; idx < 1024; idx += 256) {
                int row = idx >> 4, c = idx & 15;
                uint32_t dst = sb + SM_B + ((ch + 1) & 1) * 16384 + swz(row, c);
                cpasync16(dst, B + (size_t)(n0 + 64 + row) * CDIM + c * 8);
            }
            asm volatile("cp.async.commit_group;");
            asm volatile("cp.async.wait_group 1;");
        } else {
            asm volatile("cp.async.wait_group 0;");
        }
        __syncthreads();

        const uint32_t bb = sb + SM_B + (ch & 1) * 16384;

        float d[2][4][4];
#pragma unroll
        for (int mi = 0; mi < 2; mi++)
#pragma unroll
            for (int ni = 0; ni < 4; ni++)
#pragma unroll
                for (int q = 0; q < 4; q++) d[mi][ni][q] = 0.f;

#pragma unroll
        for (int ks = 0; ks < 8; ks++) {
            const int chunk = ks * 2 + lchunk;
            uint32_t a_h[2][4];
#pragma unroll
            for (int mi = 0; mi < 2; mi++) {
                int arow = wm * 32 + mi * 16 + lrow;
                ldsm_x4(a_h[mi][0], a_h[mi][1], a_h[mi][2], a_h[mi][3],
                        sb + SM_AH + swz(arow, chunk));
            }
#pragma unroll
            for (int nj = 0; nj < 2; nj++) {
                int brow = wn * 32 + nj * 16 + lrow;
                uint32_t r0, r1, r2, r3;
                ldsm_x4(r0, r1, r2, r3, bb + swz(brow, chunk));
                uint32_t b0[2] = {r0, r2}, b1[2] = {r1, r3};
#pragma unroll
                for (int mi = 0; mi < 2; mi++) {
                    mma16816h(d[mi][2 * nj], a_h[mi], b0);
                    mma16816h(d[mi][2 * nj + 1], a_h[mi], b1);
                }
            }
        }
        __syncthreads();   // compute done before next prefetch overwrites buffer

#pragma unroll
        for (int mi = 0; mi < 2; mi++) {
            const int mrow = m0 + wm * 32 + mi * 16 + (lane >> 2);
#pragma unroll
            for (int ni = 0; ni < 4; ni++) {
                const int ncol = n0 + wn * 32 + ni * 8 + (lane & 3) * 2;
                if (QKV) {
                    // q block (cols 0..127) pre-scaled for log2-domain softmax
                    const float sc = (ncol < 128) ? (SCALE * LOG2E) : 1.f;
                    size_t p0 = (size_t)mrow * KVN + ncol;
                    size_t p1 = (size_t)(mrow + 8) * KVN + ncol;
                    *(uint32_t*)(g_qkvh + p0) =
                        pack2h(d[mi][ni][0] * sc, d[mi][ni][1] * sc);
                    *(uint32_t*)(g_qkvh + p1) =
                        pack2h(d[mi][ni][2] * sc, d[mi][ni][3] * sc);
                } else {
                    float b0 = bias[ncol];
                    float b1 = bias[ncol + 1];
                    float* p0 = Cout + (size_t)mrow * CDIM + ncol;
                    float* p1 = Cout + (size_t)(mrow + 8) * CDIM + ncol;
                    *(float2*)p0 = make_float2(d[mi][ni][0] + b0, d[mi][ni][1] + b1);
                    *(float2*)p1 = make_float2(d[mi][ni][2] + b0, d[mi][ni][3] + b1);
                }
            }
        }
    }
}

// ============================================================
// HMMA flash attention (fp16, log2-domain softmax):
//   one CTA per (b,h), 8 warps, 3 CTAs/SM
//   Q/K/V single fp16 rows [208][32 d], stride 80 B
//   bias pre-loaded as mma C-init; P = ex2(S - m); single EX2 per element
//   PV B-frags via ldmatrix.trans on V rows
//   column sweep in 4 passes (8/6/6/6 tiles)
// ============================================================
#define AQH 0
#define AKH 16640
#define AVH 33280
#define ATTN_SMEM 49920

template<int NSTART, int NT>
__device__ __forceinline__ void half_pass(
    uint32_t qh, uint32_t kh, uint32_t vh,
    const float* __restrict__ bias0, const float* __restrict__ bias1,
    int m0, int lane,
    float o[4][4], float& mo0, float& mo1, float& sum0, float& sum1)
{
    const int lrow = lane & 15, lhalf = lane >> 4;

    // ---- init S with bias (log2 domain, mask pre-folded) ----
    float S[NT][4];
#pragma unroll
    for (int j = 0; j < NT; j++) {
        float2 v0 = *(const float2*)(bias0 + NSTART * 8 + j * 8);
        float2 v1 = *(const float2*)(bias1 + NSTART * 8 + j * 8);
        S[j][0] = v0.x; S[j][1] = v0.y;
        S[j][2] = v1.x; S[j][3] = v1.y;
    }

    // ---- QK^T accumulates onto bias ----
#pragma unroll
    for (int k0 = 0; k0 < 2; k0++) {
        uint32_t aoff = (uint32_t)((m0 + lrow) * 80 + (k0 * 2 + lhalf) * 16);
        uint32_t a_h[4];
        ldsm_x4(a_h[0], a_h[1], a_h[2], a_h[3], qh + aoff);
#pragma unroll
        for (int np = 0; np < NT / 2; np++) {
            uint32_t r0, r1, r2, r3;
            ldsm_x4(r0, r1, r2, r3,
                    kh + (uint32_t)(((NSTART + 2 * np) * 8 + lrow) * 80
                                    + (k0 * 2 + lhalf) * 16));
            uint32_t b0[2] = {r0, r2}, b1[2] = {r1, r3};
            mma16816h(S[2 * np], a_h, b0);
            mma16816h(S[2 * np + 1], a_h, b1);
        }
    }

    // ---- row max ----
    float ml0 = -1e30f, ml1 = -1e30f;
#pragma unroll
    for (int j = 0; j < NT; j++) {
        ml0 = fmaxf(ml0, fmaxf(S[j][0], S[j][1]));
        ml1 = fmaxf(ml1, fmaxf(S[j][2], S[j][3]));
    }
    ml0 = fmaxf(ml0, __shfl_xor_sync(0xffffffffu, ml0, 1));
    ml0 = fmaxf(ml0, __shfl_xor_sync(0xffffffffu, ml0, 2));
    ml1 = fmaxf(ml1, __shfl_xor_sync(0xffffffffu, ml1, 1));
    ml1 = fmaxf(ml1, __shfl_xor_sync(0xffffffffu, ml1, 2));
    float mn0 = fmaxf(mo0, ml0), mn1 = fmaxf(mo1, ml1);
    float f0 = ex2(mo0 - mn0), f1 = ex2(mo1 - mn1);
    mo0 = mn0; mo1 = mn1;
    sum0 *= f0; sum1 *= f1;
#pragma unroll
    for (int n = 0; n < 4; n++) {
        o[n][0] *= f0; o[n][1] *= f0;
        o[n][2] *= f1; o[n][3] *= f1;
    }

    // ---- P = ex2(S-m) -> fp16 frags; PV via trans-ldmatrix V ----
#pragma unroll
    for (int t = 0; t < NT / 2; t++) {
        uint32_t ah[4];
#pragma unroll
        for (int jj = 0; jj < 2; jj++) {
            int j = 2 * t + jj;
            float p0 = ex2(S[j][0] - mn0);
            float p1 = ex2(S[j][1] - mn0);
            float p2 = ex2(S[j][2] - mn1);
            float p3 = ex2(S[j][3] - mn1);
            sum0 += p0 + p1; sum1 += p2 + p3;
            ah[2 * jj]     = pack2h(p0, p1);
            ah[2 * jj + 1] = pack2h(p2, p3);
        }
        const int kk0 = NSTART * 8 + t * 16;
#pragma unroll
        for (int dh = 0; dh < 2; dh++) {       // d halves: 0..15, 16..31
            uint32_t r0, r1, r2, r3;
            ldsm_x4t(r0, r1, r2, r3,
                     vh + (uint32_t)((kk0 + lrow) * 80
                                     + (dh * 16 + lhalf * 8) * 2));
            uint32_t b0[2] = {r0, r1}, b1[2] = {r2, r3};
            mma16816h(o[2 * dh], ah, b0);
            mma16816h(o[2 * dh + 1], ah, b1);
        }
    }
}

__global__ __launch_bounds__(256, 3) void fattn_kernel()
{
    extern __shared__ char smb[];
    const uint32_t sb = smem_u32(smb);
    const int b = blockIdx.x, h = blockIdx.y;
    const int tid = threadIdx.x;

    // ---- stage q/k/v rows (pure 16B copies), all fp16 ----
    const __half* base = g_qkvh + (size_t)b * NQ * KVN + h * HD;
    for (int idx = tid; idx < 208 * 4; idx += 256) {
        int n = idx >> 2, g = idx & 3;
        int d0 = g * 8;
        uint4 qv = make_uint4(0, 0, 0, 0), kv = qv, vv = qv;
        if (n < NQ) {
            const __half* row = base + (size_t)n * KVN;
            qv = *(const uint4*)(row + d0);
            kv = *(const uint4*)(row + 128 + d0);
            vv = *(const uint4*)(row + 256 + d0);
        }
        *(uint4*)(smb + AQH + n * 80 + d0 * 2) = qv;
        *(uint4*)(smb + AKH + n * 80 + d0 * 2) = kv;
        *(uint4*)(smb + AVH + n * 80 + d0 * 2) = vv;
    }
    __syncthreads();

    const int w = tid >> 5, lane = tid & 31;
    for (int s = w; s < 13; s += 8) {
        const int m0 = s * 16;
        const int row0 = m0 + (lane >> 2), row1 = row0 + 8;
        const int rc0 = min(row0, NQ - 1), rc1 = min(row1, NQ - 1);
        const float* bias0 = g_bias + ((size_t)h * NQ + rc0) * NCP + (lane & 3) * 2;
        const float* bias1 = g_bias + ((size_t)h * NQ + rc1) * NCP + (lane & 3) * 2;

        float o[4][4];
#pragma unroll
        for (int n = 0; n < 4; n++)
#pragma unroll
            for (int q = 0; q < 4; q++) o[n][q] = 0.f;
        float mo0 = -1e30f, mo1 = -1e30f, sum0 = 0.f, sum1 = 0.f;

        half_pass<0, 8>(sb + AQH, sb + AKH, sb + AVH,
                        bias0, bias1, m0, lane, o, mo0, mo1, sum0, sum1);
        half_pass<8, 6>(sb + AQH, sb + AKH, sb + AVH,
                        bias0, bias1, m0, lane, o, mo0, mo1, sum0, sum1);
        half_pass<14, 6>(sb + AQH, sb + AKH, sb + AVH,
                         bias0, bias1, m0, lane, o, mo0, mo1, sum0, sum1);
        half_pass<20, 6>(sb + AQH, sb + AKH, sb + AVH,
                         bias0, bias1, m0, lane, o, mo0, mo1, sum0, sum1);

        sum0 += __shfl_xor_sync(0xffffffffu, sum0, 1);
        sum0 += __shfl_xor_sync(0xffffffffu, sum0, 2);
        sum1 += __shfl_xor_sync(0xffffffffu, sum1, 1);
        sum1 += __shfl_xor_sync(0xffffffffu, sum1, 2);
        float i0 = 1.f / sum0, i1 = 1.f / sum1;

#pragma unroll
        for (int n = 0; n < 4; n++) {
            int d0 = n * 8 + (lane & 3) * 2;
            if (row0 < NQ)
                *(uint32_t*)&g_atth[((size_t)b * NQ + row0) * CDIM + h * HD + d0] =
                    pack2h(o[n][0] * i0, o[n][1] * i0);
            if (row1 < NQ)
                *(uint32_t*)&g_atth[((size_t)b * NQ + row1) * CDIM + h * HD + d0] =
                    pack2h(o[n][2] * i1, o[n][3] * i1);
        }
    }
}

// ============================================================
// launch
// ============================================================
extern "C" void kernel_launch(void* const* d_in, const int* in_sizes, int n_in,
                              void* d_out, int out_size)
{
    const float* x     = (const float*)d_in[0];
    const float* wq    = (const float*)d_in[1];
    const float* wkv   = (const float*)d_in[2];
    const float* wproj = (const float*)d_in[3];
    const float* bproj = (const float*)d_in[4];
    const float* pp_w  = (const float*)d_in[5];
    const float* pp_b  = (const float*)d_in[6];
    const float* ln1_g = (const float*)d_in[7];
    const float* ln1_b = (const float*)d_in[8];
    const float* l1_w  = (const float*)d_in[9];
    const float* l1_b  = (const float*)d_in[10];
    const float* ln2_g = (const float*)d_in[11];
    const float* ln2_b = (const float*)d_in[12];
    const float* l2_w  = (const float*)d_in[13];
    const float* l2_b  = (const float*)d_in[14];
    const float* ln3_g = (const float*)d_in[15];
    const float* ln3_b = (const float*)d_in[16];
    const float* l3_w  = (const float*)d_in[17];
    const float* l3_b  = (const float*)d_in[18];
    float* out = (float*)d_out;

    cudaFuncSetAttribute(hmma_gemm_kernel<true>,
                         cudaFuncAttributeMaxDynamicSharedMemorySize, GSMEM);
    cudaFuncSetAttribute(hmma_gemm_kernel<false>,
                         cudaFuncAttributeMaxDynamicSharedMemorySize, GSMEM);
    cudaFuncSetAttribute(fattn_kernel,
                         cudaFuncAttributeMaxDynamicSharedMemorySize, ATTN_SMEM);

    pos_mlp_kernel<<<3, 256>>>(pp_w, pp_b, ln1_g, ln1_b, l1_w, l1_b,
                               ln2_g, ln2_b, l2_w, l2_b,
                               ln3_g, ln3_b, l3_w, l3_b);

    bias_prep_kernel<<<(NH * NQ * NCP + 255) / 256, 256>>>();

    wprep_kernel<<<256, 256>>>(wq, wkv, wproj);

    // QKV: x @ [wq|wkv] -> g_qkvh (fp16, q pre-scaled by SCALE*LOG2E)
    hmma_gemm_kernel<true><<<MTOT / 128, 256, GSMEM>>>(x, nullptr, nullptr);

    // flash attention (log2-domain softmax) -> g_atth (fp16)
    fattn_kernel<<<dim3(BATCH, NH), 256, ATTN_SMEM>>>();

    // Proj: att(fp16) @ wproj + bproj -> out (fp32)
    hmma_gemm_kernel<false><<<MTOT / 128, 256, GSMEM>>>(nullptr, out, bproj);
}